// round 1
// baseline (speedup 1.0000x reference)
#include <cuda_runtime.h>
#include <cstdint>

// ---------------------------------------------------------------------------
// FusionLayer collapsed to: out = relu(kmer @ A'^T + cov @ B'^T + bias')
//   A' = diag(s) * (Wf_left  @ Wk)                       [D, KMER]
//   B' = diag(s) * (Wf_right @ Wo @ Wv @ Wc)             [D, COV]
//   s  = gamma * rsqrt(running_var + eps)
//   bias' = beta + s * (bias_chain - running_mean)
// All GEMMs via mma.sync m16n8k8 TF32 (rna-rounded), fp32 accumulate.
// ---------------------------------------------------------------------------

#define DIM_B    16384
#define DIM_KMER 4096
#define DIM_COV  1024
#define DIM_D    2048
#define DIM_KTOT 5120
#define BN_EPS   1e-5f

#define BM 128
#define BN 128
#define BK 16
#define LDS_A  20   // smem leading dim for A tiles [BM][LDS_A], pad kills conflicts
#define LDS_B  20   // main: B tile stored [BN][LDS_B] (NT layout)
#define LDS_BT 136  // prep: B tile stored [BK][LDS_BT] (transposed-at-read layout)
#define STAGES 3
#define NTHREADS 256

// scratch (allocation-free rule: __device__ globals)
__device__ float g_Wcat[DIM_D * DIM_KTOT];   // packed [A' | B'] rows, tf32-rounded
__device__ float g_M1[DIM_D * DIM_COV];
__device__ float g_M2[DIM_D * DIM_COV];
__device__ float g_bias[DIM_D];
__device__ float g_t1[DIM_D];
__device__ float g_t2[DIM_D];

// ------------------------------- helpers -----------------------------------

__device__ __forceinline__ uint32_t f2tf32(float x) {
    uint32_t r;
    asm("cvt.rna.tf32.f32 %0, %1;" : "=r"(r) : "f"(x));
    return r;
}

__device__ __forceinline__ void mma_tf32(float c[4], const uint32_t a[4], const uint32_t b[2]) {
    asm volatile(
        "mma.sync.aligned.m16n8k8.row.col.f32.tf32.tf32.f32 "
        "{%0,%1,%2,%3}, {%4,%5,%6,%7}, {%8,%9}, {%0,%1,%2,%3};\n"
        : "+f"(c[0]), "+f"(c[1]), "+f"(c[2]), "+f"(c[3])
        : "r"(a[0]), "r"(a[1]), "r"(a[2]), "r"(a[3]), "r"(b[0]), "r"(b[1]));
}

__device__ __forceinline__ uint32_t smem_cast(const void* p) {
    uint32_t r;
    asm volatile("{ .reg .u64 t; cvta.to.shared.u64 t, %1; cvt.u32.u64 %0, t; }"
                 : "=r"(r) : "l"(p));
    return r;
}

__device__ __forceinline__ void cp_async16(void* sdst, const void* gsrc) {
    uint32_t d = smem_cast(sdst);
    asm volatile("cp.async.cg.shared.global [%0], [%1], 16;\n" :: "r"(d), "l"(gsrc));
}
__device__ __forceinline__ void cp_commit() { asm volatile("cp.async.commit_group;\n"); }
#define CP_WAIT(n) asm volatile("cp.async.wait_group %0;\n" :: "n"(n))

// --------------------------- main fused GEMM -------------------------------
// out[b, d] = relu( sum_{k<4096} kmer[b,k]*Wcat[d,k]
//                 + sum_{k<1024} cov[b,k]*Wcat[d,4096+k] + bias[d] )

__global__ void __launch_bounds__(NTHREADS)
main_gemm_kernel(const float* __restrict__ kmer, const float* __restrict__ cov,
                 const float* __restrict__ w, const float* __restrict__ bias,
                 float* __restrict__ out)
{
    extern __shared__ float smem[];
    float* sA = smem;                        // [STAGES][BM][LDS_A]
    float* sB = smem + STAGES * BM * LDS_A;  // [STAGES][BN][LDS_B]

    const int tid  = threadIdx.x;
    const int lane = tid & 31;
    const int wid  = tid >> 5;
    const int wm   = wid >> 2;   // 0..1  -> 64 rows
    const int wn   = wid & 3;    // 0..3  -> 32 cols
    const int g    = lane >> 2;  // groupID
    const int tg   = lane & 3;   // thread-in-group
    const int bm   = blockIdx.y, bn = blockIdx.x;

    float acc[4][4][4];
#pragma unroll
    for (int i = 0; i < 4; i++)
#pragma unroll
        for (int j = 0; j < 4; j++)
#pragma unroll
            for (int q = 0; q < 4; q++) acc[i][j][q] = 0.f;

    auto load_tile = [&](int slot, int kt) {
        float* dA = sA + slot * BM * LDS_A;
        float* dB = sB + slot * BN * LDS_B;
        int k0 = kt * BK;
        const float* xsrc; int xld, xk;
        if (k0 < DIM_KMER) { xsrc = kmer; xld = DIM_KMER; xk = k0; }
        else               { xsrc = cov;  xld = DIM_COV;  xk = k0 - DIM_KMER; }
#pragma unroll
        for (int i = 0; i < 2; i++) {
            int fid = tid + i * NTHREADS;       // 512 float4 total
            int row = fid >> 2, c4 = fid & 3;
            cp_async16(dA + row * LDS_A + c4 * 4,
                       xsrc + (size_t)(bm * BM + row) * xld + xk + c4 * 4);
        }
#pragma unroll
        for (int i = 0; i < 2; i++) {
            int fid = tid + i * NTHREADS;
            int row = fid >> 2, c4 = fid & 3;
            cp_async16(dB + row * LDS_B + c4 * 4,
                       w + (size_t)(bn * BN + row) * DIM_KTOT + k0 + c4 * 4);
        }
    };

    const int NT = DIM_KTOT / BK;   // 320
    load_tile(0, 0); cp_commit();
    load_tile(1, 1); cp_commit();

    for (int kt = 0; kt < NT; kt++) {
        CP_WAIT(STAGES - 2);
        __syncthreads();
        int pf = kt + STAGES - 1;
        if (pf < NT) load_tile(pf % STAGES, pf);
        cp_commit();

        const float* cA = sA + (kt % STAGES) * BM * LDS_A;
        const float* cB = sB + (kt % STAGES) * BN * LDS_B;
#pragma unroll
        for (int kk = 0; kk < 2; kk++) {
            uint32_t af[4][4], bfr[4][2];
#pragma unroll
            for (int mt = 0; mt < 4; mt++) {
                const float* p = cA + (wm * 64 + mt * 16 + g) * LDS_A + kk * 8 + tg;
                af[mt][0] = f2tf32(p[0]);
                af[mt][1] = f2tf32(p[8 * LDS_A]);
                af[mt][2] = f2tf32(p[4]);
                af[mt][3] = f2tf32(p[8 * LDS_A + 4]);
            }
#pragma unroll
            for (int nt = 0; nt < 4; nt++) {
                const float* p = cB + (wn * 32 + nt * 8 + g) * LDS_B + kk * 8 + tg;
                bfr[nt][0] = __float_as_uint(p[0]);   // weights pre-rounded in prep
                bfr[nt][1] = __float_as_uint(p[4]);
            }
#pragma unroll
            for (int mt = 0; mt < 4; mt++)
#pragma unroll
                for (int nt = 0; nt < 4; nt++)
                    mma_tf32(acc[mt][nt], af[mt], bfr[nt]);
        }
    }

    // epilogue: +bias, relu
#pragma unroll
    for (int mt = 0; mt < 4; mt++) {
        int row = bm * BM + wm * 64 + mt * 16 + g;
#pragma unroll
        for (int nt = 0; nt < 4; nt++) {
            int col = bn * BN + wn * 32 + nt * 8 + tg * 2;
            float b0 = bias[col], b1 = bias[col + 1];
            float2 v;
            v.x = fmaxf(acc[mt][nt][0] + b0, 0.f);
            v.y = fmaxf(acc[mt][nt][1] + b1, 0.f);
            *reinterpret_cast<float2*>(&out[(size_t)row * DIM_D + col]) = v;
            v.x = fmaxf(acc[mt][nt][2] + b0, 0.f);
            v.y = fmaxf(acc[mt][nt][3] + b1, 0.f);
            *reinterpret_cast<float2*>(&out[(size_t)(row + 8) * DIM_D + col]) = v;
        }
    }
}

// ------------------------ weight-composition GEMM --------------------------
// C[i,j] = sum_k A[i*lda + aoffs + k] * B[k*ldb + j]
// (NN; B tile staged as [BK][LDS_BT], transposed at fragment read)

__global__ void __launch_bounds__(NTHREADS)
prep_gemm_kernel(const float* __restrict__ A, int lda, int aoffs,
                 const float* __restrict__ Bg, int ldb,
                 float* __restrict__ C, int ldc, int coffs,
                 int K,
                 const float* __restrict__ gamma, const float* __restrict__ rvar,
                 int scale_round)
{
    extern __shared__ float smem[];
    float* sA  = smem;                        // [STAGES][BM][LDS_A]
    float* sBt = smem + STAGES * BM * LDS_A;  // [STAGES][BK][LDS_BT]

    const int tid  = threadIdx.x;
    const int lane = tid & 31;
    const int wid  = tid >> 5;
    const int wm   = wid >> 2;
    const int wn   = wid & 3;
    const int g    = lane >> 2;
    const int tg   = lane & 3;
    const int bm   = blockIdx.y, bn = blockIdx.x;

    float acc[4][4][4];
#pragma unroll
    for (int i = 0; i < 4; i++)
#pragma unroll
        for (int j = 0; j < 4; j++)
#pragma unroll
            for (int q = 0; q < 4; q++) acc[i][j][q] = 0.f;

    auto load_tile = [&](int slot, int kt) {
        float* dA = sA  + slot * BM * LDS_A;
        float* dB = sBt + slot * BK * LDS_BT;
        int k0 = kt * BK;
#pragma unroll
        for (int i = 0; i < 2; i++) {
            int fid = tid + i * NTHREADS;
            int row = fid >> 2, c4 = fid & 3;
            cp_async16(dA + row * LDS_A + c4 * 4,
                       A + (size_t)(bm * BM + row) * lda + aoffs + k0 + c4 * 4);
        }
#pragma unroll
        for (int i = 0; i < 2; i++) {
            int fid = tid + i * NTHREADS;      // 16 rows x 32 float4
            int r = fid >> 5, c4 = fid & 31;
            cp_async16(dB + r * LDS_BT + c4 * 4,
                       Bg + (size_t)(k0 + r) * ldb + bn * BN + c4 * 4);
        }
    };

    const int NT = K / BK;
    load_tile(0, 0); cp_commit();
    load_tile(1, 1); cp_commit();

    for (int kt = 0; kt < NT; kt++) {
        CP_WAIT(STAGES - 2);
        __syncthreads();
        int pf = kt + STAGES - 1;
        if (pf < NT) load_tile(pf % STAGES, pf);
        cp_commit();

        const float* cA = sA  + (kt % STAGES) * BM * LDS_A;
        const float* cB = sBt + (kt % STAGES) * BK * LDS_BT;
#pragma unroll
        for (int kk = 0; kk < 2; kk++) {
            uint32_t af[4][4], bfr[4][2];
#pragma unroll
            for (int mt = 0; mt < 4; mt++) {
                const float* p = cA + (wm * 64 + mt * 16 + g) * LDS_A + kk * 8 + tg;
                af[mt][0] = f2tf32(p[0]);
                af[mt][1] = f2tf32(p[8 * LDS_A]);
                af[mt][2] = f2tf32(p[4]);
                af[mt][3] = f2tf32(p[8 * LDS_A + 4]);
            }
#pragma unroll
            for (int nt = 0; nt < 4; nt++) {
                const float* p = cB + (kk * 8 + tg) * LDS_BT + wn * 32 + nt * 8 + g;
                bfr[nt][0] = f2tf32(p[0]);
                bfr[nt][1] = f2tf32(p[4 * LDS_BT]);
            }
#pragma unroll
            for (int mt = 0; mt < 4; mt++)
#pragma unroll
                for (int nt = 0; nt < 4; nt++)
                    mma_tf32(acc[mt][nt], af[mt], bfr[nt]);
        }
    }

#pragma unroll
    for (int mt = 0; mt < 4; mt++) {
        int row0 = bm * BM + wm * 64 + mt * 16 + g;
        float s0 = 1.f, s1 = 1.f;
        if (scale_round) {
            s0 = gamma[row0]     * rsqrtf(rvar[row0]     + BN_EPS);
            s1 = gamma[row0 + 8] * rsqrtf(rvar[row0 + 8] + BN_EPS);
        }
#pragma unroll
        for (int nt = 0; nt < 4; nt++) {
            int col = bn * BN + wn * 32 + nt * 8 + tg * 2;
            float v0 = acc[mt][nt][0] * s0;
            float v1 = acc[mt][nt][1] * s0;
            float v2 = acc[mt][nt][2] * s1;
            float v3 = acc[mt][nt][3] * s1;
            if (scale_round) {   // pre-round composed weights to tf32 (rna)
                v0 = __uint_as_float(f2tf32(v0));
                v1 = __uint_as_float(f2tf32(v1));
                v2 = __uint_as_float(f2tf32(v2));
                v3 = __uint_as_float(f2tf32(v3));
            }
            C[(size_t)row0 * ldc + coffs + col]           = v0;
            C[(size_t)row0 * ldc + coffs + col + 1]       = v1;
            C[(size_t)(row0 + 8) * ldc + coffs + col]     = v2;
            C[(size_t)(row0 + 8) * ldc + coffs + col + 1] = v3;
        }
    }
}

// ------------------------------ bias chain ---------------------------------

__global__ void matvec_kernel(const float* __restrict__ A, int lda, int aoffs,
                              const float* __restrict__ x, int K,
                              const float* __restrict__ addv,
                              float* __restrict__ y, int accum)
{
    int i = blockIdx.x;
    const float* arow = A + (size_t)i * lda + aoffs;
    float s = 0.f;
    for (int k = threadIdx.x; k < K; k += blockDim.x) s += arow[k] * x[k];
#pragma unroll
    for (int o = 16; o > 0; o >>= 1) s += __shfl_xor_sync(0xffffffffu, s, o);
    __shared__ float red[8];
    if ((threadIdx.x & 31) == 0) red[threadIdx.x >> 5] = s;
    __syncthreads();
    if (threadIdx.x == 0) {
        float t = 0.f;
        for (int w = 0; w < (int)(blockDim.x >> 5); w++) t += red[w];
        if (addv) t += addv[i];
        if (accum) t += y[i];
        y[i] = t;
    }
}

__global__ void bias_finalize_kernel(float* __restrict__ bias,
                                     const float* __restrict__ beta,
                                     const float* __restrict__ mean,
                                     const float* __restrict__ gamma,
                                     const float* __restrict__ rvar)
{
    int j = blockIdx.x * blockDim.x + threadIdx.x;
    if (j < DIM_D) {
        float s = gamma[j] * rsqrtf(rvar[j] + BN_EPS);
        bias[j] = beta[j] + s * (bias[j] - mean[j]);
    }
}

// ------------------------------- launcher ----------------------------------

extern "C" void kernel_launch(void* const* d_in, const int* in_sizes, int n_in,
                              void* d_out, int out_size)
{
    const float* kmer  = (const float*)d_in[0];
    const float* cov   = (const float*)d_in[1];
    const float* Wk    = (const float*)d_in[2];
    const float* bk    = (const float*)d_in[3];
    const float* Wc    = (const float*)d_in[4];
    const float* bc    = (const float*)d_in[5];
    const float* Wv    = (const float*)d_in[6];
    const float* bv    = (const float*)d_in[7];
    const float* Wo    = (const float*)d_in[8];
    const float* bo    = (const float*)d_in[9];
    const float* Wf    = (const float*)d_in[10];
    const float* bf    = (const float*)d_in[11];
    const float* gamma = (const float*)d_in[12];
    const float* beta  = (const float*)d_in[13];
    const float* mean  = (const float*)d_in[14];
    const float* var   = (const float*)d_in[15];
    float* out = (float*)d_out;

    float *Wcat, *M1, *M2, *bias, *t1, *t2;
    cudaGetSymbolAddress((void**)&Wcat, g_Wcat);
    cudaGetSymbolAddress((void**)&M1,   g_M1);
    cudaGetSymbolAddress((void**)&M2,   g_M2);
    cudaGetSymbolAddress((void**)&bias, g_bias);
    cudaGetSymbolAddress((void**)&t1,   g_t1);
    cudaGetSymbolAddress((void**)&t2,   g_t2);

    const int smem_main = STAGES * (BM * LDS_A + BN * LDS_B) * (int)sizeof(float);   // 60 KB
    const int smem_prep = STAGES * (BM * LDS_A + BK * LDS_BT) * (int)sizeof(float);  // ~55.5 KB
    cudaFuncSetAttribute(main_gemm_kernel, cudaFuncAttributeMaxDynamicSharedMemorySize, smem_main);
    cudaFuncSetAttribute(prep_gemm_kernel, cudaFuncAttributeMaxDynamicSharedMemorySize, smem_prep);

    // bias chain: t1 = Wv@bc + bv; t2 = Wo@t1 + bo; bias = Wf_r@t2 + bf + Wf_l@bk
    matvec_kernel<<<DIM_D, 256>>>(Wv, DIM_D, 0,      bc, DIM_D, bv,      t1,   0);
    matvec_kernel<<<DIM_D, 256>>>(Wo, DIM_D, 0,      t1, DIM_D, bo,      t2,   0);
    matvec_kernel<<<DIM_D, 256>>>(Wf, 2 * DIM_D, DIM_D, t2, DIM_D, bf,   bias, 0);
    matvec_kernel<<<DIM_D, 256>>>(Wf, 2 * DIM_D, 0,  bk, DIM_D, nullptr, bias, 1);

    // weight composition
    dim3 gridP1(DIM_COV / BN, DIM_D / BM);    // (8, 16)
    prep_gemm_kernel<<<gridP1, NTHREADS, smem_prep>>>(Wv, DIM_D, 0,        Wc, DIM_COV,
                                                      M1, DIM_COV, 0, DIM_D, nullptr, nullptr, 0);
    prep_gemm_kernel<<<gridP1, NTHREADS, smem_prep>>>(Wo, DIM_D, 0,        M1, DIM_COV,
                                                      M2, DIM_COV, 0, DIM_D, nullptr, nullptr, 0);
    prep_gemm_kernel<<<gridP1, NTHREADS, smem_prep>>>(Wf, 2 * DIM_D, DIM_D, M2, DIM_COV,
                                                      Wcat, DIM_KTOT, DIM_KMER, DIM_D, gamma, var, 1);
    dim3 gridP4(DIM_KMER / BN, DIM_D / BM);   // (32, 16)
    prep_gemm_kernel<<<gridP4, NTHREADS, smem_prep>>>(Wf, 2 * DIM_D, 0,    Wk, DIM_KMER,
                                                      Wcat, DIM_KTOT, 0, DIM_D, gamma, var, 1);

    bias_finalize_kernel<<<(DIM_D + 255) / 256, 256>>>(bias, beta, mean, gamma, var);

    // main fused GEMM + BN + ReLU
    dim3 gridM(DIM_D / BN, DIM_B / BM);       // (16, 128)
    main_gemm_kernel<<<gridM, NTHREADS, smem_main>>>(kmer, cov, Wcat, bias, out);
}

// round 3
// speedup vs baseline: 1.1467x; 1.1467x over previous
#include <cuda_runtime.h>
#include <cstdint>

// ---------------------------------------------------------------------------
// FusionLayer collapsed to: out = relu(X @ Wcat^T + bias')
//   X    = [kmer | cov], rna-rounded to tf32, k-cols fragment-permuted
//   Wcat = [A' | B'],  A' = s*(Wf_l @ Wk), B' = s*(Wf_r @ Wo @ Wv @ Wc)
//   (same permutation applied by prep epilogue)
// Main GEMM: mma.sync m16n8k8 tf32, 64x64 warp tiles, float4 fragment loads.
// NOTE: tcgen05.ld/st/wait are rejected by this toolchain's compute_103 PTX
// target (arch-specific subset), so TMEM accumulators are unusable here.
// ---------------------------------------------------------------------------

#define DIM_B    16384
#define DIM_KMER 4096
#define DIM_COV  1024
#define DIM_D    2048
#define DIM_KTOT 5120
#define BN_EPS   1e-5f

// scratch (allocation-free rule: __device__ globals)
__device__ float g_X[(size_t)DIM_B * DIM_KTOT];     // rounded+permuted activations
__device__ float g_Wcat[DIM_D * DIM_KTOT];          // [A' | B'], rounded+permuted
__device__ float g_M1[DIM_D * DIM_COV];
__device__ float g_M2[DIM_D * DIM_COV];
__device__ float g_bias[DIM_D];
__device__ float g_t1[DIM_D];
__device__ float g_t2[DIM_D];

// ------------------------------- helpers -----------------------------------

__device__ __forceinline__ uint32_t f2tf32(float x) {
    uint32_t r;
    asm("cvt.rna.tf32.f32 %0, %1;" : "=r"(r) : "f"(x));
    return r;
}

__device__ __forceinline__ uint32_t smem_cast(const void* p) {
    uint32_t r;
    asm volatile("{ .reg .u64 t; cvta.to.shared.u64 t, %1; cvt.u32.u64 %0, t; }"
                 : "=r"(r) : "l"(p));
    return r;
}

__device__ __forceinline__ void cp_async16(void* sdst, const void* gsrc) {
    uint32_t d = smem_cast(sdst);
    asm volatile("cp.async.cg.shared.global [%0], [%1], 16;\n" :: "r"(d), "l"(gsrc));
}

__device__ __forceinline__ void mma_tf32(float c[4], const uint32_t a[4], const uint32_t b[2]) {
    asm volatile(
        "mma.sync.aligned.m16n8k8.row.col.f32.tf32.tf32.f32 "
        "{%0,%1,%2,%3}, {%4,%5,%6,%7}, {%8,%9}, {%0,%1,%2,%3};\n"
        : "+f"(c[0]), "+f"(c[1]), "+f"(c[2]), "+f"(c[3])
        : "r"(a[0]), "r"(a[1]), "r"(a[2]), "r"(a[3]), "r"(b[0]), "r"(b[1]));
}

// fragment permutation within a 16-col k-group: col c -> 4*(c&3) + (c>>2)
__device__ __forceinline__ int perm16(int c) {
    return (c & ~15) | (((c & 3) << 2) | ((c >> 2) & 3));
}

// ========================= main fused GEMM ==================================
// 128x128 CTA tile, 4 warps of 64x64, BK=16, 5-stage cp.async pipeline.

#define BM 128
#define BN 128
#define BK 16
#define MSTG 5
#define MTHREADS 128
#define MNKT (DIM_KTOT / BK)          // 320
#define MSTAGE_BYTES (2 * BM * BK * 4) // A 8KB + B 8KB = 16KB
#define MSMEM_TOTAL (MSTG * MSTAGE_BYTES)

__global__ void __launch_bounds__(MTHREADS, 2)
main_gemm_kernel(const float* __restrict__ X, const float* __restrict__ W,
                 const float* __restrict__ bias, float* __restrict__ out)
{
    extern __shared__ char smem[];
    const int tid  = threadIdx.x;
    const int lane = tid & 31;
    const int wid  = tid >> 5;        // 0..3, one warp per SMSP
    const int wm   = wid >> 1;        // 0..1 -> 64 rows
    const int wn   = wid & 1;         // 0..1 -> 64 cols
    const int g    = lane >> 2;       // 0..7
    const int tg   = lane & 3;        // 0..3
    const int bn   = blockIdx.x, bm = blockIdx.y;

    const float* gA = X + (size_t)(bm * BM) * DIM_KTOT;
    const float* gB = W + (size_t)(bn * BN) * DIM_KTOT;

    float acc[4][8][4];
#pragma unroll
    for (int i = 0; i < 4; i++)
#pragma unroll
        for (int j = 0; j < 8; j++)
#pragma unroll
            for (int q = 0; q < 4; q++) acc[i][j][q] = 0.f;

    auto load_tile = [&](int slot, int kt) {
        char* stg = smem + slot * MSTAGE_BYTES;
        const int k0 = kt * BK;
#pragma unroll
        for (int i = 0; i < 4; i++) {            // A: 512 float4, 128 thr -> 4 each
            int fid = tid + i * MTHREADS;
            int row = fid >> 2, c4 = fid & 3;
            cp_async16(stg + row * 64 + c4 * 16,
                       gA + (size_t)row * DIM_KTOT + k0 + c4 * 4);
        }
#pragma unroll
        for (int i = 0; i < 4; i++) {            // B
            int fid = tid + i * MTHREADS;
            int row = fid >> 2, c4 = fid & 3;
            cp_async16(stg + 8192 + row * 64 + c4 * 16,
                       gB + (size_t)row * DIM_KTOT + k0 + c4 * 4);
        }
        asm volatile("cp.async.commit_group;\n");
    };

#pragma unroll
    for (int s = 0; s < MSTG - 1; s++) load_tile(s, s);

    for (int kt = 0; kt < MNKT; kt++) {
        asm volatile("cp.async.wait_group %0;\n" :: "n"(MSTG - 2));
        __syncthreads();
        const int pf = kt + MSTG - 1;
        if (pf < MNKT) load_tile(pf % MSTG, pf);
        else asm volatile("cp.async.commit_group;\n");

        const uint4* pa = reinterpret_cast<const uint4*>(smem + (kt % MSTG) * MSTAGE_BYTES);
        const uint4* pb = reinterpret_cast<const uint4*>(smem + (kt % MSTG) * MSTAGE_BYTES + 8192);

        uint4 Af[8], Bf[8];
#pragma unroll
        for (int mt = 0; mt < 4; mt++) {
            Af[2 * mt]     = pa[(wm * 64 + mt * 16 + g) * 4 + tg];
            Af[2 * mt + 1] = pa[(wm * 64 + mt * 16 + g + 8) * 4 + tg];
        }
#pragma unroll
        for (int nt = 0; nt < 8; nt++)
            Bf[nt] = pb[(wn * 64 + nt * 8 + g) * 4 + tg];

#pragma unroll
        for (int kk = 0; kk < 2; kk++) {
#pragma unroll
            for (int mt = 0; mt < 4; mt++) {
                uint32_t af[4];
                if (kk == 0) {
                    af[0] = Af[2 * mt].x; af[1] = Af[2 * mt + 1].x;
                    af[2] = Af[2 * mt].y; af[3] = Af[2 * mt + 1].y;
                } else {
                    af[0] = Af[2 * mt].z; af[1] = Af[2 * mt + 1].z;
                    af[2] = Af[2 * mt].w; af[3] = Af[2 * mt + 1].w;
                }
#pragma unroll
                for (int nt = 0; nt < 8; nt++) {
                    uint32_t bf[2];
                    if (kk == 0) { bf[0] = Bf[nt].x; bf[1] = Bf[nt].y; }
                    else         { bf[0] = Bf[nt].z; bf[1] = Bf[nt].w; }
                    mma_tf32(acc[mt][nt], af, bf);
                }
            }
        }
    }

    // epilogue: +bias, relu
#pragma unroll
    for (int mt = 0; mt < 4; mt++) {
        int row = bm * BM + wm * 64 + mt * 16 + g;
#pragma unroll
        for (int nt = 0; nt < 8; nt++) {
            int col = bn * BN + wn * 64 + nt * 8 + tg * 2;
            float b0 = bias[col], b1 = bias[col + 1];
            float2 v;
            v.x = fmaxf(acc[mt][nt][0] + b0, 0.f);
            v.y = fmaxf(acc[mt][nt][1] + b1, 0.f);
            *reinterpret_cast<float2*>(&out[(size_t)row * DIM_D + col]) = v;
            v.x = fmaxf(acc[mt][nt][2] + b0, 0.f);
            v.y = fmaxf(acc[mt][nt][3] + b1, 0.f);
            *reinterpret_cast<float2*>(&out[(size_t)(row + 8) * DIM_D + col]) = v;
        }
    }
}

// ================= round + permute + pack activations =======================
// dst[b][dstoff + group*16 + 4*(c&3)+(c>>2)] = rna_tf32(src[b][group*16 + c])

__global__ void round_pack_perm(const float* __restrict__ src, int lw,
                                int dstoff, float* __restrict__ dst)
{
    const int width = 1 << lw;
    const int glog = lw - 4;
    const size_t total = (size_t)DIM_B << glog;
    for (size_t gi = (size_t)blockIdx.x * blockDim.x + threadIdx.x; gi < total;
         gi += (size_t)gridDim.x * blockDim.x) {
        const int b = (int)(gi >> glog);
        const int grp = (int)(gi & ((1 << glog) - 1));
        const float4* s = reinterpret_cast<const float4*>(src + (size_t)b * width + grp * 16);
        float4 v[4];
#pragma unroll
        for (int j = 0; j < 4; j++) {
            v[j] = s[j];
            v[j].x = __uint_as_float(f2tf32(v[j].x));
            v[j].y = __uint_as_float(f2tf32(v[j].y));
            v[j].z = __uint_as_float(f2tf32(v[j].z));
            v[j].w = __uint_as_float(f2tf32(v[j].w));
        }
        float4* d = reinterpret_cast<float4*>(dst + (size_t)b * DIM_KTOT + dstoff + grp * 16);
        d[0] = make_float4(v[0].x, v[1].x, v[2].x, v[3].x);   // cols {0,4,8,12}
        d[1] = make_float4(v[0].y, v[1].y, v[2].y, v[3].y);   // cols {1,5,9,13}
        d[2] = make_float4(v[0].z, v[1].z, v[2].z, v[3].z);   // cols {2,6,10,14}
        d[3] = make_float4(v[0].w, v[1].w, v[2].w, v[3].w);   // cols {3,7,11,15}
    }
}

// ===================== prep GEMMs (mma.sync tf32, R1 core) ==================

#define PBM 128
#define PBN 128
#define PBK 16
#define LDS_A  20
#define LDS_BT 136
#define PSTAGES 3
#define PNTHREADS 256

__global__ void __launch_bounds__(PNTHREADS)
prep_gemm_kernel(const float* __restrict__ A, int lda, int aoffs,
                 const float* __restrict__ Bg, int ldb,
                 float* __restrict__ C, int ldc, int coffs, int K,
                 const float* __restrict__ gamma, const float* __restrict__ rvar,
                 int scale_round)
{
    extern __shared__ float fsm[];
    float* sA  = fsm;
    float* sBt = fsm + PSTAGES * PBM * LDS_A;

    const int tid  = threadIdx.x;
    const int lane = tid & 31;
    const int wid  = tid >> 5;
    const int wm   = wid >> 2;
    const int wn   = wid & 3;
    const int g    = lane >> 2;
    const int tg   = lane & 3;
    const int bm   = blockIdx.y, bn = blockIdx.x;

    float acc[4][4][4];
#pragma unroll
    for (int i = 0; i < 4; i++)
#pragma unroll
        for (int j = 0; j < 4; j++)
#pragma unroll
            for (int q = 0; q < 4; q++) acc[i][j][q] = 0.f;

    auto load_tile = [&](int slot, int kt) {
        float* dA = sA  + slot * PBM * LDS_A;
        float* dB = sBt + slot * PBK * LDS_BT;
        int k0 = kt * PBK;
#pragma unroll
        for (int i = 0; i < 2; i++) {
            int fid = tid + i * PNTHREADS;
            int row = fid >> 2, c4 = fid & 3;
            cp_async16(dA + row * LDS_A + c4 * 4,
                       A + (size_t)(bm * PBM + row) * lda + aoffs + k0 + c4 * 4);
        }
#pragma unroll
        for (int i = 0; i < 2; i++) {
            int fid = tid + i * PNTHREADS;
            int r = fid >> 5, c4 = fid & 31;
            cp_async16(dB + r * LDS_BT + c4 * 4,
                       Bg + (size_t)(k0 + r) * ldb + bn * PBN + c4 * 4);
        }
    };

    const int NT = K / PBK;
    load_tile(0, 0); asm volatile("cp.async.commit_group;\n");
    load_tile(1, 1); asm volatile("cp.async.commit_group;\n");

    for (int kt = 0; kt < NT; kt++) {
        asm volatile("cp.async.wait_group %0;\n" :: "n"(PSTAGES - 2));
        __syncthreads();
        int pf = kt + PSTAGES - 1;
        if (pf < NT) load_tile(pf % PSTAGES, pf);
        asm volatile("cp.async.commit_group;\n");

        const float* cA = sA  + (kt % PSTAGES) * PBM * LDS_A;
        const float* cB = sBt + (kt % PSTAGES) * PBK * LDS_BT;
#pragma unroll
        for (int kk = 0; kk < 2; kk++) {
            uint32_t af[4][4], bfr[4][2];
#pragma unroll
            for (int mt = 0; mt < 4; mt++) {
                const float* p = cA + (wm * 64 + mt * 16 + g) * LDS_A + kk * 8 + tg;
                af[mt][0] = f2tf32(p[0]);
                af[mt][1] = f2tf32(p[8 * LDS_A]);
                af[mt][2] = f2tf32(p[4]);
                af[mt][3] = f2tf32(p[8 * LDS_A + 4]);
            }
#pragma unroll
            for (int nt = 0; nt < 4; nt++) {
                const float* p = cB + (kk * 8 + tg) * LDS_BT + wn * 32 + nt * 8 + g;
                bfr[nt][0] = f2tf32(p[0]);
                bfr[nt][1] = f2tf32(p[4 * LDS_BT]);
            }
#pragma unroll
            for (int mt = 0; mt < 4; mt++)
#pragma unroll
                for (int nt = 0; nt < 4; nt++)
                    mma_tf32(acc[mt][nt], af[mt], bfr[nt]);
        }
    }

#pragma unroll
    for (int mt = 0; mt < 4; mt++) {
        int row0 = bm * PBM + wm * 64 + mt * 16 + g;
        float s0 = 1.f, s1 = 1.f;
        if (scale_round) {
            s0 = gamma[row0]     * rsqrtf(rvar[row0]     + BN_EPS);
            s1 = gamma[row0 + 8] * rsqrtf(rvar[row0 + 8] + BN_EPS);
        }
#pragma unroll
        for (int nt = 0; nt < 4; nt++) {
            int col = bn * PBN + wn * 32 + nt * 8 + tg * 2;
            float v0 = acc[mt][nt][0] * s0;
            float v1 = acc[mt][nt][1] * s0;
            float v2 = acc[mt][nt][2] * s1;
            float v3 = acc[mt][nt][3] * s1;
            if (scale_round) {
                // round to tf32 and store PERMUTED (consumed by main kernel)
                int cA0 = perm16(col), cA1 = perm16(col + 1);
                C[(size_t)row0 * ldc + coffs + cA0]       = __uint_as_float(f2tf32(v0));
                C[(size_t)row0 * ldc + coffs + cA1]       = __uint_as_float(f2tf32(v1));
                C[(size_t)(row0 + 8) * ldc + coffs + cA0] = __uint_as_float(f2tf32(v2));
                C[(size_t)(row0 + 8) * ldc + coffs + cA1] = __uint_as_float(f2tf32(v3));
            } else {
                C[(size_t)row0 * ldc + coffs + col]           = v0;
                C[(size_t)row0 * ldc + coffs + col + 1]       = v1;
                C[(size_t)(row0 + 8) * ldc + coffs + col]     = v2;
                C[(size_t)(row0 + 8) * ldc + coffs + col + 1] = v3;
            }
        }
    }
}

// ------------------------------ bias chain ---------------------------------

__global__ void matvec_kernel(const float* __restrict__ A, int lda, int aoffs,
                              const float* __restrict__ x, int K,
                              const float* __restrict__ addv,
                              float* __restrict__ y, int accum)
{
    int i = blockIdx.x;
    const float* arow = A + (size_t)i * lda + aoffs;
    float s = 0.f;
    for (int k = threadIdx.x; k < K; k += blockDim.x) s += arow[k] * x[k];
#pragma unroll
    for (int o = 16; o > 0; o >>= 1) s += __shfl_xor_sync(0xffffffffu, s, o);
    __shared__ float red[8];
    if ((threadIdx.x & 31) == 0) red[threadIdx.x >> 5] = s;
    __syncthreads();
    if (threadIdx.x == 0) {
        float t = 0.f;
        for (int w = 0; w < (int)(blockDim.x >> 5); w++) t += red[w];
        if (addv) t += addv[i];
        if (accum) t += y[i];
        y[i] = t;
    }
}

__global__ void bias_finalize_kernel(float* __restrict__ bias,
                                     const float* __restrict__ beta,
                                     const float* __restrict__ mean,
                                     const float* __restrict__ gamma,
                                     const float* __restrict__ rvar)
{
    int j = blockIdx.x * blockDim.x + threadIdx.x;
    if (j < DIM_D) {
        float s = gamma[j] * rsqrtf(rvar[j] + BN_EPS);
        bias[j] = beta[j] + s * (bias[j] - mean[j]);
    }
}

// ------------------------------- launcher ----------------------------------

extern "C" void kernel_launch(void* const* d_in, const int* in_sizes, int n_in,
                              void* d_out, int out_size)
{
    const float* kmer  = (const float*)d_in[0];
    const float* cov   = (const float*)d_in[1];
    const float* Wk    = (const float*)d_in[2];
    const float* bk    = (const float*)d_in[3];
    const float* Wc    = (const float*)d_in[4];
    const float* bc    = (const float*)d_in[5];
    const float* Wv    = (const float*)d_in[6];
    const float* bv    = (const float*)d_in[7];
    const float* Wo    = (const float*)d_in[8];
    const float* bo    = (const float*)d_in[9];
    const float* Wf    = (const float*)d_in[10];
    const float* bf    = (const float*)d_in[11];
    const float* gamma = (const float*)d_in[12];
    const float* beta  = (const float*)d_in[13];
    const float* mean  = (const float*)d_in[14];
    const float* var   = (const float*)d_in[15];
    float* out = (float*)d_out;

    float *X, *Wcat, *M1, *M2, *bias, *t1, *t2;
    cudaGetSymbolAddress((void**)&X,    g_X);
    cudaGetSymbolAddress((void**)&Wcat, g_Wcat);
    cudaGetSymbolAddress((void**)&M1,   g_M1);
    cudaGetSymbolAddress((void**)&M2,   g_M2);
    cudaGetSymbolAddress((void**)&bias, g_bias);
    cudaGetSymbolAddress((void**)&t1,   g_t1);
    cudaGetSymbolAddress((void**)&t2,   g_t2);

    const int smem_prep = PSTAGES * (PBM * LDS_A + PBK * LDS_BT) * (int)sizeof(float);
    cudaFuncSetAttribute(prep_gemm_kernel, cudaFuncAttributeMaxDynamicSharedMemorySize, smem_prep);
    cudaFuncSetAttribute(main_gemm_kernel, cudaFuncAttributeMaxDynamicSharedMemorySize, MSMEM_TOTAL);

    // activation round + permute + pack
    round_pack_perm<<<4096, 256>>>(kmer, 12, 0,        X);
    round_pack_perm<<<1024, 256>>>(cov,  10, DIM_KMER, X);

    // bias chain
    matvec_kernel<<<DIM_D, 256>>>(Wv, DIM_D, 0,          bc, DIM_D, bv,      t1,   0);
    matvec_kernel<<<DIM_D, 256>>>(Wo, DIM_D, 0,          t1, DIM_D, bo,      t2,   0);
    matvec_kernel<<<DIM_D, 256>>>(Wf, 2 * DIM_D, DIM_D,  t2, DIM_D, bf,      bias, 0);
    matvec_kernel<<<DIM_D, 256>>>(Wf, 2 * DIM_D, 0,      bk, DIM_D, nullptr, bias, 1);

    // weight composition
    dim3 gridP1(DIM_COV / PBN, DIM_D / PBM);
    prep_gemm_kernel<<<gridP1, PNTHREADS, smem_prep>>>(Wv, DIM_D, 0,         Wc, DIM_COV,
                                                       M1, DIM_COV, 0, DIM_D, nullptr, nullptr, 0);
    prep_gemm_kernel<<<gridP1, PNTHREADS, smem_prep>>>(Wo, DIM_D, 0,         M1, DIM_COV,
                                                       M2, DIM_COV, 0, DIM_D, nullptr, nullptr, 0);
    prep_gemm_kernel<<<gridP1, PNTHREADS, smem_prep>>>(Wf, 2 * DIM_D, DIM_D, M2, DIM_COV,
                                                       Wcat, DIM_KTOT, DIM_KMER, DIM_D, gamma, var, 1);
    dim3 gridP4(DIM_KMER / PBN, DIM_D / PBM);
    prep_gemm_kernel<<<gridP4, PNTHREADS, smem_prep>>>(Wf, 2 * DIM_D, 0,     Wk, DIM_KMER,
                                                       Wcat, DIM_KTOT, 0, DIM_D, gamma, var, 1);

    bias_finalize_kernel<<<(DIM_D + 255) / 256, 256>>>(bias, beta, mean, gamma, var);

    // main fused GEMM + bias + ReLU
    dim3 gridM(DIM_D / BN, DIM_B / BM);   // (16, 128)
    main_gemm_kernel<<<gridM, MTHREADS, MSMEM_TOTAL>>>(X, Wcat, bias, out);
}

// round 4
// speedup vs baseline: 1.3392x; 1.1678x over previous
#include <cuda_runtime.h>
#include <cstdint>

// ---------------------------------------------------------------------------
// FusionLayer collapsed to: out = relu(X @ Wcat^T + bias')
//   X    = [kmer | cov], rna-rounded tf32, packed [B, 5120] (K-major)
//   Wcat = [A' | B'],  A' = s*(Wf_l @ Wk), B' = s*(Wf_r @ Wo @ Wv @ Wc)
// One fast NT GEMM core (mma.sync m16n8k8 tf32, 64x64 warp tiles, float4
// fragment loads, BK=32, 3-stage cp.async) used for BOTH the main GEMM and
// all weight-composition GEMMs (inputs made NT via transpose kernels).
// No k-permutation needed: mma pairs A/B fragments position-wise, so any
// consistent within-group k ordering is correct.
// ---------------------------------------------------------------------------

#define DIM_B    16384
#define DIM_KMER 4096
#define DIM_COV  1024
#define DIM_D    2048
#define DIM_KTOT 5120
#define BN_EPS   1e-5f

// scratch (allocation-free rule: __device__ globals)
__device__ float g_X[(size_t)DIM_B * DIM_KTOT];     // rounded activations
__device__ float g_Wcat[DIM_D * DIM_KTOT];          // [A' | B'], rounded
__device__ float g_WcT[DIM_COV * DIM_D];            // Wc^T  [1024, 2048]
__device__ float g_WkT[DIM_KMER * DIM_D];           // Wk^T  [4096, 2048]
__device__ float g_M1t[DIM_COV * DIM_D];            // (Wv@Wc)^T
__device__ float g_M2t[DIM_COV * DIM_D];            // (Wo@Wv@Wc)^T
__device__ float g_bias[DIM_D];
__device__ float g_t1[DIM_D];
__device__ float g_t2[DIM_D];

// ------------------------------- helpers -----------------------------------

__device__ __forceinline__ uint32_t f2tf32(float x) {
    uint32_t r;
    asm("cvt.rna.tf32.f32 %0, %1;" : "=r"(r) : "f"(x));
    return r;
}

__device__ __forceinline__ uint32_t smem_cast(const void* p) {
    uint32_t r;
    asm volatile("{ .reg .u64 t; cvta.to.shared.u64 t, %1; cvt.u32.u64 %0, t; }"
                 : "=r"(r) : "l"(p));
    return r;
}

__device__ __forceinline__ void cp_async16(void* sdst, const void* gsrc) {
    uint32_t d = smem_cast(sdst);
    asm volatile("cp.async.cg.shared.global [%0], [%1], 16;\n" :: "r"(d), "l"(gsrc));
}

__device__ __forceinline__ void mma_tf32(float c[4], const uint32_t a[4], const uint32_t b[2]) {
    asm volatile(
        "mma.sync.aligned.m16n8k8.row.col.f32.tf32.tf32.f32 "
        "{%0,%1,%2,%3}, {%4,%5,%6,%7}, {%8,%9}, {%0,%1,%2,%3};\n"
        : "+f"(c[0]), "+f"(c[1]), "+f"(c[2]), "+f"(c[3])
        : "r"(a[0]), "r"(a[1]), "r"(a[2]), "r"(a[3]), "r"(b[0]), "r"(b[1]));
}

// ====================== unified fast NT GEMM core ===========================
// C-tile 128x128, 4 warps of 64x64, BK=32, 3-stage cp.async pipeline.
// A [M,K] K-major (lda), Bt [N,K] K-major (ldb). EPI: 0 = bias+relu store,
// 1 = transposed raw store, 2 = per-row scale + rna-round store (+coffs).

#define GSTG 3
#define GSTAGE_BYTES 32768
#define GSMEM_TOTAL (GSTG * GSTAGE_BYTES)   // 96 KB

template<int EPI, bool ROUND>
__global__ void __launch_bounds__(128, 2)
gemm_nt_kernel(const float* __restrict__ A, int lda,
               const float* __restrict__ Bt, int ldb,
               float* __restrict__ C, int ldc, int coffs, int K,
               const float* __restrict__ aux1, const float* __restrict__ aux2)
{
    extern __shared__ char smem[];
    const int tid  = threadIdx.x;
    const int lane = tid & 31;
    const int wid  = tid >> 5;
    const int wm   = wid >> 1;        // 0..1 -> 64 rows
    const int wn   = wid & 1;         // 0..1 -> 64 cols
    const int g    = lane >> 2;       // 0..7
    const int tg   = lane & 3;        // 0..3
    const int bn   = blockIdx.x, bm = blockIdx.y;

    const float* gA = A  + (size_t)(bm * 128) * lda;
    const float* gB = Bt + (size_t)(bn * 128) * ldb;

    float acc[4][8][4];
#pragma unroll
    for (int i = 0; i < 4; i++)
#pragma unroll
        for (int j = 0; j < 8; j++)
#pragma unroll
            for (int q = 0; q < 4; q++) acc[i][j][q] = 0.f;

    auto load_tile = [&](int slot, int kt) {
        char* stg = smem + slot * GSTAGE_BYTES;
        const int k0 = kt * 32;
#pragma unroll
        for (int i = 0; i < 8; i++) {            // A: 128 rows x 128B
            int fid = tid + i * 128;
            int row = fid >> 3, c = fid & 7;
            cp_async16(stg + row * 128 + c * 16,
                       gA + (size_t)row * lda + k0 + c * 4);
        }
#pragma unroll
        for (int i = 0; i < 8; i++) {            // B: 128 rows x 128B
            int fid = tid + i * 128;
            int row = fid >> 3, c = fid & 7;
            cp_async16(stg + 16384 + row * 128 + c * 16,
                       gB + (size_t)row * ldb + k0 + c * 4);
        }
        asm volatile("cp.async.commit_group;\n");
    };

    const int NKT = K / 32;
    load_tile(0, 0);
    load_tile(1, 1);

    for (int kt = 0; kt < NKT; kt++) {
        asm volatile("cp.async.wait_group %0;\n" :: "n"(1));
        __syncthreads();
        if (kt + 2 < NKT) load_tile((kt + 2) % GSTG, kt + 2);
        else asm volatile("cp.async.commit_group;\n");

        const uint4* pa = reinterpret_cast<const uint4*>(smem + (kt % GSTG) * GSTAGE_BYTES);
        const uint4* pb = reinterpret_cast<const uint4*>(smem + (kt % GSTG) * GSTAGE_BYTES + 16384);

#pragma unroll
        for (int h = 0; h < 2; h++) {            // two k16 halves of BK=32
            uint4 Af[8], Bf[8];
#pragma unroll
            for (int mt = 0; mt < 4; mt++) {
                Af[2 * mt]     = pa[(wm * 64 + mt * 16 + g) * 8 + h * 4 + tg];
                Af[2 * mt + 1] = pa[(wm * 64 + mt * 16 + g + 8) * 8 + h * 4 + tg];
            }
#pragma unroll
            for (int nt = 0; nt < 8; nt++)
                Bf[nt] = pb[(wn * 64 + nt * 8 + g) * 8 + h * 4 + tg];

            if (ROUND) {
#pragma unroll
                for (int i = 0; i < 8; i++) {
                    Af[i].x = f2tf32(__uint_as_float(Af[i].x));
                    Af[i].y = f2tf32(__uint_as_float(Af[i].y));
                    Af[i].z = f2tf32(__uint_as_float(Af[i].z));
                    Af[i].w = f2tf32(__uint_as_float(Af[i].w));
                    Bf[i].x = f2tf32(__uint_as_float(Bf[i].x));
                    Bf[i].y = f2tf32(__uint_as_float(Bf[i].y));
                    Bf[i].z = f2tf32(__uint_as_float(Bf[i].z));
                    Bf[i].w = f2tf32(__uint_as_float(Bf[i].w));
                }
            }

#pragma unroll
            for (int kk = 0; kk < 2; kk++) {
#pragma unroll
                for (int mt = 0; mt < 4; mt++) {
                    uint32_t af[4];
                    if (kk == 0) {
                        af[0] = Af[2 * mt].x; af[1] = Af[2 * mt + 1].x;
                        af[2] = Af[2 * mt].y; af[3] = Af[2 * mt + 1].y;
                    } else {
                        af[0] = Af[2 * mt].z; af[1] = Af[2 * mt + 1].z;
                        af[2] = Af[2 * mt].w; af[3] = Af[2 * mt + 1].w;
                    }
#pragma unroll
                    for (int nt = 0; nt < 8; nt++) {
                        uint32_t bf[2];
                        if (kk == 0) { bf[0] = Bf[nt].x; bf[1] = Bf[nt].y; }
                        else         { bf[0] = Bf[nt].z; bf[1] = Bf[nt].w; }
                        mma_tf32(acc[mt][nt], af, bf);
                    }
                }
            }
        }
    }

    // ------------------------------ epilogue --------------------------------
#pragma unroll
    for (int mt = 0; mt < 4; mt++) {
        const int row = bm * 128 + wm * 64 + mt * 16 + g;
        float s0 = 1.f, s1 = 1.f;
        if (EPI == 2) {
            s0 = aux1[row]     * rsqrtf(aux2[row]     + BN_EPS);
            s1 = aux1[row + 8] * rsqrtf(aux2[row + 8] + BN_EPS);
        }
#pragma unroll
        for (int nt = 0; nt < 8; nt++) {
            const int col = bn * 128 + wn * 64 + nt * 8 + tg * 2;
            if (EPI == 0) {
                float b0 = aux1[col], b1 = aux1[col + 1];
                float2 v;
                v.x = fmaxf(acc[mt][nt][0] + b0, 0.f);
                v.y = fmaxf(acc[mt][nt][1] + b1, 0.f);
                *reinterpret_cast<float2*>(&C[(size_t)row * ldc + col]) = v;
                v.x = fmaxf(acc[mt][nt][2] + b0, 0.f);
                v.y = fmaxf(acc[mt][nt][3] + b1, 0.f);
                *reinterpret_cast<float2*>(&C[(size_t)(row + 8) * ldc + col]) = v;
            } else if (EPI == 1) {
                C[(size_t)col * ldc + row]           = acc[mt][nt][0];
                C[(size_t)(col + 1) * ldc + row]     = acc[mt][nt][1];
                C[(size_t)col * ldc + row + 8]       = acc[mt][nt][2];
                C[(size_t)(col + 1) * ldc + row + 8] = acc[mt][nt][3];
            } else {
                C[(size_t)row * ldc + coffs + col]           = __uint_as_float(f2tf32(acc[mt][nt][0] * s0));
                C[(size_t)row * ldc + coffs + col + 1]       = __uint_as_float(f2tf32(acc[mt][nt][1] * s0));
                C[(size_t)(row + 8) * ldc + coffs + col]     = __uint_as_float(f2tf32(acc[mt][nt][2] * s1));
                C[(size_t)(row + 8) * ldc + coffs + col + 1] = __uint_as_float(f2tf32(acc[mt][nt][3] * s1));
            }
        }
    }
}

// ====================== round + pack activations ============================

__global__ void round_pack(const float* __restrict__ src, int lw,
                           int dstoff, float* __restrict__ dst)
{
    const size_t n4 = ((size_t)DIM_B << lw) >> 2;
    const int w4log = lw - 2;
    for (size_t i = (size_t)blockIdx.x * blockDim.x + threadIdx.x; i < n4;
         i += (size_t)gridDim.x * blockDim.x) {
        const int b = (int)(i >> w4log);
        const int r = (int)(i & ((1u << w4log) - 1));
        float4 v = reinterpret_cast<const float4*>(src)[i];
        v.x = __uint_as_float(f2tf32(v.x));
        v.y = __uint_as_float(f2tf32(v.y));
        v.z = __uint_as_float(f2tf32(v.z));
        v.w = __uint_as_float(f2tf32(v.w));
        *reinterpret_cast<float4*>(dst + (size_t)b * DIM_KTOT + dstoff + r * 4) = v;
    }
}

// ============================ transpose =====================================
// outT[j, i] = in[i, j];  in is [R, Cc] row-major.

__global__ void transpose_kernel(const float* __restrict__ in, float* __restrict__ outT,
                                 int R, int Cc)
{
    __shared__ float t[32][33];
    const int bx = blockIdx.x * 32, by = blockIdx.y * 32;
    int x = bx + threadIdx.x;
    int y = by + threadIdx.y;
#pragma unroll
    for (int j = 0; j < 32; j += 8)
        t[threadIdx.y + j][threadIdx.x] = in[(size_t)(y + j) * Cc + x];
    __syncthreads();
    x = by + threadIdx.x;
    y = bx + threadIdx.y;
#pragma unroll
    for (int j = 0; j < 32; j += 8)
        outT[(size_t)(y + j) * R + x] = t[threadIdx.x][threadIdx.y + j];
}

// ============================ bias chain ====================================

__global__ void matvec_kernel(const float* __restrict__ A, int lda, int aoffs,
                              const float* __restrict__ x, int K,
                              const float* __restrict__ addv,
                              float* __restrict__ y, int accum)
{
    int i = blockIdx.x;
    const float* arow = A + (size_t)i * lda + aoffs;
    float s = 0.f;
    for (int k = threadIdx.x; k < K; k += blockDim.x) s += arow[k] * x[k];
#pragma unroll
    for (int o = 16; o > 0; o >>= 1) s += __shfl_xor_sync(0xffffffffu, s, o);
    __shared__ float red[8];
    if ((threadIdx.x & 31) == 0) red[threadIdx.x >> 5] = s;
    __syncthreads();
    if (threadIdx.x == 0) {
        float t = 0.f;
        for (int w = 0; w < (int)(blockDim.x >> 5); w++) t += red[w];
        if (addv) t += addv[i];
        if (accum) t += y[i];
        y[i] = t;
    }
}

__global__ void bias_finalize_kernel(float* __restrict__ bias,
                                     const float* __restrict__ beta,
                                     const float* __restrict__ mean,
                                     const float* __restrict__ gamma,
                                     const float* __restrict__ rvar)
{
    int j = blockIdx.x * blockDim.x + threadIdx.x;
    if (j < DIM_D) {
        float s = gamma[j] * rsqrtf(rvar[j] + BN_EPS);
        bias[j] = beta[j] + s * (bias[j] - mean[j]);
    }
}

// ------------------------------- launcher ----------------------------------

extern "C" void kernel_launch(void* const* d_in, const int* in_sizes, int n_in,
                              void* d_out, int out_size)
{
    const float* kmer  = (const float*)d_in[0];
    const float* cov   = (const float*)d_in[1];
    const float* Wk    = (const float*)d_in[2];
    const float* bk    = (const float*)d_in[3];
    const float* Wc    = (const float*)d_in[4];
    const float* bc    = (const float*)d_in[5];
    const float* Wv    = (const float*)d_in[6];
    const float* bv    = (const float*)d_in[7];
    const float* Wo    = (const float*)d_in[8];
    const float* bo    = (const float*)d_in[9];
    const float* Wf    = (const float*)d_in[10];
    const float* bf    = (const float*)d_in[11];
    const float* gamma = (const float*)d_in[12];
    const float* beta  = (const float*)d_in[13];
    const float* mean  = (const float*)d_in[14];
    const float* var   = (const float*)d_in[15];
    float* out = (float*)d_out;

    float *X, *Wcat, *WcT, *WkT, *M1t, *M2t, *bias, *t1, *t2;
    cudaGetSymbolAddress((void**)&X,    g_X);
    cudaGetSymbolAddress((void**)&Wcat, g_Wcat);
    cudaGetSymbolAddress((void**)&WcT,  g_WcT);
    cudaGetSymbolAddress((void**)&WkT,  g_WkT);
    cudaGetSymbolAddress((void**)&M1t,  g_M1t);
    cudaGetSymbolAddress((void**)&M2t,  g_M2t);
    cudaGetSymbolAddress((void**)&bias, g_bias);
    cudaGetSymbolAddress((void**)&t1,   g_t1);
    cudaGetSymbolAddress((void**)&t2,   g_t2);

    cudaFuncSetAttribute(gemm_nt_kernel<0, false>, cudaFuncAttributeMaxDynamicSharedMemorySize, GSMEM_TOTAL);
    cudaFuncSetAttribute(gemm_nt_kernel<1, true>,  cudaFuncAttributeMaxDynamicSharedMemorySize, GSMEM_TOTAL);
    cudaFuncSetAttribute(gemm_nt_kernel<2, true>,  cudaFuncAttributeMaxDynamicSharedMemorySize, GSMEM_TOTAL);

    // 0,1: activation rounding + packing
    round_pack<<<4096, 256>>>(kmer, 12, 0,        X);
    round_pack<<<1024, 256>>>(cov,  10, DIM_KMER, X);

    // 2,3: transposes (make weight GEMMs NT-layout)
    {
        dim3 blk(32, 8);
        dim3 gc(DIM_COV / 32,  DIM_D / 32);
        dim3 gk(DIM_KMER / 32, DIM_D / 32);
        transpose_kernel<<<gc, blk>>>(Wc, WcT, DIM_D, DIM_COV);
        transpose_kernel<<<gk, blk>>>(Wk, WkT, DIM_D, DIM_KMER);
    }

    // 4: M1t = (Wv @ Wc)^T          [1024, 2048]
    {
        dim3 grid(DIM_COV / 128, DIM_D / 128);   // (8, 16)
        gemm_nt_kernel<1, true><<<grid, 128, GSMEM_TOTAL>>>(
            Wv, DIM_D, WcT, DIM_D, M1t, DIM_D, 0, DIM_D, nullptr, nullptr);
    }
    // 5: Wcat left = s*(Wf_l @ Wk)  (BIG one — profiled by ncu -s 5)
    {
        dim3 grid(DIM_KMER / 128, DIM_D / 128);  // (32, 16)
        gemm_nt_kernel<2, true><<<grid, 128, GSMEM_TOTAL>>>(
            Wf, 2 * DIM_D, WkT, DIM_D, Wcat, DIM_KTOT, 0, DIM_D, gamma, var);
    }
    // 6: M2t = (Wo @ M1)^T
    {
        dim3 grid(DIM_COV / 128, DIM_D / 128);
        gemm_nt_kernel<1, true><<<grid, 128, GSMEM_TOTAL>>>(
            Wo, DIM_D, M1t, DIM_D, M2t, DIM_D, 0, DIM_D, nullptr, nullptr);
    }
    // 7: Wcat right = s*(Wf_r @ M2)
    {
        dim3 grid(DIM_COV / 128, DIM_D / 128);
        gemm_nt_kernel<2, true><<<grid, 128, GSMEM_TOTAL>>>(
            Wf + DIM_D, 2 * DIM_D, M2t, DIM_D, Wcat, DIM_KTOT, DIM_KMER, DIM_D, gamma, var);
    }

    // 8-11: bias chain
    matvec_kernel<<<DIM_D, 256>>>(Wv, DIM_D, 0,          bc, DIM_D, bv,      t1,   0);
    matvec_kernel<<<DIM_D, 256>>>(Wo, DIM_D, 0,          t1, DIM_D, bo,      t2,   0);
    matvec_kernel<<<DIM_D, 256>>>(Wf, 2 * DIM_D, DIM_D,  t2, DIM_D, bf,      bias, 0);
    matvec_kernel<<<DIM_D, 256>>>(Wf, 2 * DIM_D, 0,      bk, DIM_D, nullptr, bias, 1);

    // 12: fold BN into bias
    bias_finalize_kernel<<<(DIM_D + 255) / 256, 256>>>(bias, beta, mean, gamma, var);

    // 13: main fused GEMM + bias + ReLU
    {
        dim3 grid(DIM_D / 128, DIM_B / 128);     // (16, 128)
        gemm_nt_kernel<0, false><<<grid, 128, GSMEM_TOTAL>>>(
            X, DIM_KTOT, Wcat, DIM_KTOT, out, DIM_D, 0, DIM_KTOT, bias, nullptr);
    }
}

// round 5
// speedup vs baseline: 2.1658x; 1.6172x over previous
#include <cuda_runtime.h>
#include <cuda_fp16.h>
#include <cstdint>

// ---------------------------------------------------------------------------
// FusionLayer collapsed to: out = relu(X @ Wcat^T + bias')
//   X    = [kmer | cov] -> fp16 (rn), b32-permuted, packed [B, 5120]
//   Wcat = [A' | B'] composed in tf32 GEMMs, stored fp16 b32-permuted
// Main GEMM: mma.sync m16n8k16 f16 (fp32 accum) — 2x MACs/instruction vs
// tf32 m16n8k8 (same 11-bit significand => same error class).
// b32 permutation within each 32-col block: dst b32 (4t+s) = orig (t+4s),
// so one LDS.128 supplies a thread's fragment regs for two k16 groups.
// ---------------------------------------------------------------------------

#define DIM_B    16384
#define DIM_KMER 4096
#define DIM_COV  1024
#define DIM_D    2048
#define DIM_KTOT 5120
#define BN_EPS   1e-5f

// scratch (allocation-free rule: __device__ globals)
__device__ __half g_Xh[(size_t)DIM_B * DIM_KTOT];   // fp16 permuted activations
__device__ __half g_Wh[DIM_D * DIM_KTOT];           // fp16 permuted [A' | B']
__device__ float  g_WcT[DIM_COV * DIM_D];
__device__ float  g_WkT[DIM_KMER * DIM_D];
__device__ float  g_M1t[DIM_COV * DIM_D];
__device__ float  g_M2t[DIM_COV * DIM_D];
__device__ float  g_bias[DIM_D];
__device__ float  g_t1[DIM_D];
__device__ float  g_t2[DIM_D];

// ------------------------------- helpers -----------------------------------

__device__ __forceinline__ uint32_t f2tf32(float x) {
    uint32_t r;
    asm("cvt.rna.tf32.f32 %0, %1;" : "=r"(r) : "f"(x));
    return r;
}

__device__ __forceinline__ uint32_t smem_cast(const void* p) {
    uint32_t r;
    asm volatile("{ .reg .u64 t; cvta.to.shared.u64 t, %1; cvt.u32.u64 %0, t; }"
                 : "=r"(r) : "l"(p));
    return r;
}

__device__ __forceinline__ void cp_async16(void* sdst, const void* gsrc) {
    uint32_t d = smem_cast(sdst);
    asm volatile("cp.async.cg.shared.global [%0], [%1], 16;\n" :: "r"(d), "l"(gsrc));
}

__device__ __forceinline__ void mma_tf32(float c[4], const uint32_t a[4], const uint32_t b[2]) {
    asm volatile(
        "mma.sync.aligned.m16n8k8.row.col.f32.tf32.tf32.f32 "
        "{%0,%1,%2,%3}, {%4,%5,%6,%7}, {%8,%9}, {%0,%1,%2,%3};\n"
        : "+f"(c[0]), "+f"(c[1]), "+f"(c[2]), "+f"(c[3])
        : "r"(a[0]), "r"(a[1]), "r"(a[2]), "r"(a[3]), "r"(b[0]), "r"(b[1]));
}

__device__ __forceinline__ void mma_fp16(float c[4], uint32_t a0, uint32_t a1,
                                         uint32_t a2, uint32_t a3,
                                         uint32_t b0, uint32_t b1) {
    asm volatile(
        "mma.sync.aligned.m16n8k16.row.col.f32.f16.f16.f32 "
        "{%0,%1,%2,%3}, {%4,%5,%6,%7}, {%8,%9}, {%0,%1,%2,%3};\n"
        : "+f"(c[0]), "+f"(c[1]), "+f"(c[2]), "+f"(c[3])
        : "r"(a0), "r"(a1), "r"(a2), "r"(a3), "r"(b0), "r"(b1));
}

__device__ __forceinline__ uint32_t pack_h2(float lo, float hi) {
    __half2 h = __floats2half2_rn(lo, hi);
    return *reinterpret_cast<uint32_t*>(&h);
}

// ===================== main fused GEMM (fp16 operands) ======================
// C-tile 128x128, 4 warps of 64x64, BK=64 (128B rows), 3-stage cp.async.
// smem rows XOR-swizzled by 64B on odd rows (kills 2-way LDS phase conflict).

#define HSTG 3
#define HSTAGE_BYTES 32768            // A 16KB + B 16KB
#define HSMEM_TOTAL (HSTG * HSTAGE_BYTES)
#define HNKT (DIM_KTOT / 64)          // 80

__global__ void __launch_bounds__(128, 2)
main_gemm_fp16(const __half* __restrict__ X, const __half* __restrict__ W,
               const float* __restrict__ bias, float* __restrict__ out)
{
    extern __shared__ char smem[];
    const int tid  = threadIdx.x;
    const int lane = tid & 31;
    const int wid  = tid >> 5;
    const int wm   = wid >> 1;
    const int wn   = wid & 1;
    const int g    = lane >> 2;
    const int tg   = lane & 3;
    const int bn   = blockIdx.x, bm = blockIdx.y;

    const __half* gA = X + (size_t)(bm * 128) * DIM_KTOT;
    const __half* gB = W + (size_t)(bn * 128) * DIM_KTOT;

    float acc[4][8][4];
#pragma unroll
    for (int i = 0; i < 4; i++)
#pragma unroll
        for (int j = 0; j < 8; j++)
#pragma unroll
            for (int q = 0; q < 4; q++) acc[i][j][q] = 0.f;

    auto load_tile = [&](int slot, int kt) {
        char* stg = smem + slot * HSTAGE_BYTES;
        const int k0 = kt * 64;
#pragma unroll
        for (int i = 0; i < 8; i++) {            // A: 128 rows x 128B
            int fid = tid + i * 128;
            int row = fid >> 3, c = fid & 7;
            cp_async16(stg + row * 128 + ((c * 16) ^ ((row & 1) << 6)),
                       gA + (size_t)row * DIM_KTOT + k0 + c * 8);
        }
#pragma unroll
        for (int i = 0; i < 8; i++) {            // B
            int fid = tid + i * 128;
            int row = fid >> 3, c = fid & 7;
            cp_async16(stg + 16384 + row * 128 + ((c * 16) ^ ((row & 1) << 6)),
                       gB + (size_t)row * DIM_KTOT + k0 + c * 8);
        }
        asm volatile("cp.async.commit_group;\n");
    };

    load_tile(0, 0);
    load_tile(1, 1);

    for (int kt = 0; kt < HNKT; kt++) {
        asm volatile("cp.async.wait_group %0;\n" :: "n"(1));
        __syncthreads();
        if (kt + 2 < HNKT) load_tile((kt + 2) % HSTG, kt + 2);
        else asm volatile("cp.async.commit_group;\n");

        const char* pa = smem + (kt % HSTG) * HSTAGE_BYTES;
        const char* pb = pa + 16384;

#pragma unroll
        for (int b = 0; b < 2; b++) {            // two 64B (k32) blocks
            uint4 Af[8], Bf[8];
#pragma unroll
            for (int mt = 0; mt < 4; mt++) {
                int r0 = wm * 64 + mt * 16 + g;
                int r1 = r0 + 8;
                Af[2 * mt] = *reinterpret_cast<const uint4*>(
                    pa + r0 * 128 + ((b * 64 + tg * 16) ^ ((r0 & 1) << 6)));
                Af[2 * mt + 1] = *reinterpret_cast<const uint4*>(
                    pa + r1 * 128 + ((b * 64 + tg * 16) ^ ((r1 & 1) << 6)));
            }
#pragma unroll
            for (int nt = 0; nt < 8; nt++) {
                int r = wn * 64 + nt * 8 + g;
                Bf[nt] = *reinterpret_cast<const uint4*>(
                    pb + r * 128 + ((b * 64 + tg * 16) ^ ((r & 1) << 6)));
            }
            // permuted layout: .x/.y = group0 (k lo/hi), .z/.w = group1
#pragma unroll
            for (int grp = 0; grp < 2; grp++) {
#pragma unroll
                for (int mt = 0; mt < 4; mt++) {
                    uint32_t a0, a1, a2, a3;
                    if (grp == 0) {
                        a0 = Af[2 * mt].x; a1 = Af[2 * mt + 1].x;
                        a2 = Af[2 * mt].y; a3 = Af[2 * mt + 1].y;
                    } else {
                        a0 = Af[2 * mt].z; a1 = Af[2 * mt + 1].z;
                        a2 = Af[2 * mt].w; a3 = Af[2 * mt + 1].w;
                    }
#pragma unroll
                    for (int nt = 0; nt < 8; nt++) {
                        uint32_t b0, b1;
                        if (grp == 0) { b0 = Bf[nt].x; b1 = Bf[nt].y; }
                        else          { b0 = Bf[nt].z; b1 = Bf[nt].w; }
                        mma_fp16(acc[mt][nt], a0, a1, a2, a3, b0, b1);
                    }
                }
            }
        }
    }

    // epilogue: +bias, relu
#pragma unroll
    for (int mt = 0; mt < 4; mt++) {
        const int row = bm * 128 + wm * 64 + mt * 16 + g;
#pragma unroll
        for (int nt = 0; nt < 8; nt++) {
            const int col = bn * 128 + wn * 64 + nt * 8 + tg * 2;
            float b0 = bias[col], b1 = bias[col + 1];
            float2 v;
            v.x = fmaxf(acc[mt][nt][0] + b0, 0.f);
            v.y = fmaxf(acc[mt][nt][1] + b1, 0.f);
            *reinterpret_cast<float2*>(&out[(size_t)row * DIM_D + col]) = v;
            v.x = fmaxf(acc[mt][nt][2] + b0, 0.f);
            v.y = fmaxf(acc[mt][nt][3] + b1, 0.f);
            *reinterpret_cast<float2*>(&out[(size_t)(row + 8) * DIM_D + col]) = v;
        }
    }
}

// ================== tf32 NT GEMM core (weight composition) ==================
// EPI 1: transposed fp32 raw store. EPI 2: per-row BN scale + fp16 permuted
// store into Wh (C reinterpreted as uint32_t*, ldc given in b32 units).

#define GSTG 3
#define GSTAGE_BYTES 32768
#define GSMEM_TOTAL (GSTG * GSTAGE_BYTES)

template<int EPI>
__global__ void __launch_bounds__(128, 2)
gemm_nt_kernel(const float* __restrict__ A, int lda,
               const float* __restrict__ Bt, int ldb,
               float* __restrict__ C, int ldc, int coffs, int K,
               const float* __restrict__ aux1, const float* __restrict__ aux2)
{
    extern __shared__ char smem[];
    const int tid  = threadIdx.x;
    const int lane = tid & 31;
    const int wid  = tid >> 5;
    const int wm   = wid >> 1;
    const int wn   = wid & 1;
    const int g    = lane >> 2;
    const int tg   = lane & 3;
    const int bn   = blockIdx.x, bm = blockIdx.y;

    const float* gA = A  + (size_t)(bm * 128) * lda;
    const float* gB = Bt + (size_t)(bn * 128) * ldb;

    float acc[4][8][4];
#pragma unroll
    for (int i = 0; i < 4; i++)
#pragma unroll
        for (int j = 0; j < 8; j++)
#pragma unroll
            for (int q = 0; q < 4; q++) acc[i][j][q] = 0.f;

    auto load_tile = [&](int slot, int kt) {
        char* stg = smem + slot * GSTAGE_BYTES;
        const int k0 = kt * 32;
#pragma unroll
        for (int i = 0; i < 8; i++) {
            int fid = tid + i * 128;
            int row = fid >> 3, c = fid & 7;
            cp_async16(stg + row * 128 + c * 16,
                       gA + (size_t)row * lda + k0 + c * 4);
        }
#pragma unroll
        for (int i = 0; i < 8; i++) {
            int fid = tid + i * 128;
            int row = fid >> 3, c = fid & 7;
            cp_async16(stg + 16384 + row * 128 + c * 16,
                       gB + (size_t)row * ldb + k0 + c * 4);
        }
        asm volatile("cp.async.commit_group;\n");
    };

    const int NKT = K / 32;
    load_tile(0, 0);
    load_tile(1, 1);

    for (int kt = 0; kt < NKT; kt++) {
        asm volatile("cp.async.wait_group %0;\n" :: "n"(1));
        __syncthreads();
        if (kt + 2 < NKT) load_tile((kt + 2) % GSTG, kt + 2);
        else asm volatile("cp.async.commit_group;\n");

        const uint4* pa = reinterpret_cast<const uint4*>(smem + (kt % GSTG) * GSTAGE_BYTES);
        const uint4* pb = reinterpret_cast<const uint4*>(smem + (kt % GSTG) * GSTAGE_BYTES + 16384);

#pragma unroll
        for (int h = 0; h < 2; h++) {
            uint4 Af[8], Bf[8];
#pragma unroll
            for (int mt = 0; mt < 4; mt++) {
                Af[2 * mt]     = pa[(wm * 64 + mt * 16 + g) * 8 + h * 4 + tg];
                Af[2 * mt + 1] = pa[(wm * 64 + mt * 16 + g + 8) * 8 + h * 4 + tg];
            }
#pragma unroll
            for (int nt = 0; nt < 8; nt++)
                Bf[nt] = pb[(wn * 64 + nt * 8 + g) * 8 + h * 4 + tg];

#pragma unroll
            for (int i = 0; i < 8; i++) {
                Af[i].x = f2tf32(__uint_as_float(Af[i].x));
                Af[i].y = f2tf32(__uint_as_float(Af[i].y));
                Af[i].z = f2tf32(__uint_as_float(Af[i].z));
                Af[i].w = f2tf32(__uint_as_float(Af[i].w));
                Bf[i].x = f2tf32(__uint_as_float(Bf[i].x));
                Bf[i].y = f2tf32(__uint_as_float(Bf[i].y));
                Bf[i].z = f2tf32(__uint_as_float(Bf[i].z));
                Bf[i].w = f2tf32(__uint_as_float(Bf[i].w));
            }

#pragma unroll
            for (int kk = 0; kk < 2; kk++) {
#pragma unroll
                for (int mt = 0; mt < 4; mt++) {
                    uint32_t af[4];
                    if (kk == 0) {
                        af[0] = Af[2 * mt].x; af[1] = Af[2 * mt + 1].x;
                        af[2] = Af[2 * mt].y; af[3] = Af[2 * mt + 1].y;
                    } else {
                        af[0] = Af[2 * mt].z; af[1] = Af[2 * mt + 1].z;
                        af[2] = Af[2 * mt].w; af[3] = Af[2 * mt + 1].w;
                    }
#pragma unroll
                    for (int nt = 0; nt < 8; nt++) {
                        uint32_t bf[2];
                        if (kk == 0) { bf[0] = Bf[nt].x; bf[1] = Bf[nt].y; }
                        else         { bf[0] = Bf[nt].z; bf[1] = Bf[nt].w; }
                        mma_tf32(acc[mt][nt], af, bf);
                    }
                }
            }
        }
    }

#pragma unroll
    for (int mt = 0; mt < 4; mt++) {
        const int row = bm * 128 + wm * 64 + mt * 16 + g;
        float s0 = 1.f, s1 = 1.f;
        if (EPI == 2) {
            s0 = aux1[row]     * rsqrtf(aux2[row]     + BN_EPS);
            s1 = aux1[row + 8] * rsqrtf(aux2[row + 8] + BN_EPS);
        }
#pragma unroll
        for (int nt = 0; nt < 8; nt++) {
            const int col = bn * 128 + wn * 64 + nt * 8 + tg * 2;
            if (EPI == 1) {
                C[(size_t)col * ldc + row]           = acc[mt][nt][0];
                C[(size_t)(col + 1) * ldc + row]     = acc[mt][nt][1];
                C[(size_t)col * ldc + row + 8]       = acc[mt][nt][2];
                C[(size_t)(col + 1) * ldc + row + 8] = acc[mt][nt][3];
            } else {
                // fp16 permuted store into Wh: ldc = b32 row stride (2560)
                uint32_t* Ch = reinterpret_cast<uint32_t*>(C);
                int j = (coffs + col) >> 1;                 // global b32 index
                int dst = (j & ~15) + 4 * (j & 3) + ((j & 15) >> 2);
                Ch[(size_t)row * ldc + dst]       = pack_h2(acc[mt][nt][0] * s0,
                                                            acc[mt][nt][1] * s0);
                Ch[(size_t)(row + 8) * ldc + dst] = pack_h2(acc[mt][nt][2] * s1,
                                                            acc[mt][nt][3] * s1);
            }
        }
    }
}

// =============== pack activations: fp32 -> fp16, b32-permuted ===============
// one thread per 32-col block: dst uint4 t = {h[t], h[t+4], h[t+8], h[t+12]}

__global__ void pack_fp16(const float* __restrict__ src, int lw,
                          int dstoff, __half* __restrict__ dst)
{
    const int nblk = 1 << (lw - 5);           // 32-col blocks per row
    const size_t total = (size_t)DIM_B << (lw - 5);
    for (size_t idx = (size_t)blockIdx.x * blockDim.x + threadIdx.x; idx < total;
         idx += (size_t)gridDim.x * blockDim.x) {
        const int b   = (int)(idx >> (lw - 5));
        const int blk = (int)(idx & (nblk - 1));
        const float4* s = reinterpret_cast<const float4*>(
            src + ((size_t)b << lw) + blk * 32);
        uint32_t h[16];
#pragma unroll
        for (int i = 0; i < 8; i++) {
            float4 v = s[i];
            h[2 * i]     = pack_h2(v.x, v.y);
            h[2 * i + 1] = pack_h2(v.z, v.w);
        }
        uint4* d = reinterpret_cast<uint4*>(
            dst + (size_t)b * DIM_KTOT + dstoff + blk * 32);
#pragma unroll
        for (int t = 0; t < 4; t++)
            d[t] = make_uint4(h[t], h[t + 4], h[t + 8], h[t + 12]);
    }
}

// ============================ transpose =====================================

__global__ void transpose_kernel(const float* __restrict__ in, float* __restrict__ outT,
                                 int R, int Cc)
{
    __shared__ float t[32][33];
    const int bx = blockIdx.x * 32, by = blockIdx.y * 32;
    int x = bx + threadIdx.x;
    int y = by + threadIdx.y;
#pragma unroll
    for (int j = 0; j < 32; j += 8)
        t[threadIdx.y + j][threadIdx.x] = in[(size_t)(y + j) * Cc + x];
    __syncthreads();
    x = by + threadIdx.x;
    y = bx + threadIdx.y;
#pragma unroll
    for (int j = 0; j < 32; j += 8)
        outT[(size_t)(y + j) * R + x] = t[threadIdx.x][threadIdx.y + j];
}

// ============================ bias chain ====================================

__global__ void matvec_kernel(const float* __restrict__ A, int lda, int aoffs,
                              const float* __restrict__ x, int K,
                              const float* __restrict__ addv,
                              float* __restrict__ y, int accum)
{
    int i = blockIdx.x;
    const float* arow = A + (size_t)i * lda + aoffs;
    float s = 0.f;
    for (int k = threadIdx.x; k < K; k += blockDim.x) s += arow[k] * x[k];
#pragma unroll
    for (int o = 16; o > 0; o >>= 1) s += __shfl_xor_sync(0xffffffffu, s, o);
    __shared__ float red[8];
    if ((threadIdx.x & 31) == 0) red[threadIdx.x >> 5] = s;
    __syncthreads();
    if (threadIdx.x == 0) {
        float t = 0.f;
        for (int w = 0; w < (int)(blockDim.x >> 5); w++) t += red[w];
        if (addv) t += addv[i];
        if (accum) t += y[i];
        y[i] = t;
    }
}

__global__ void bias_finalize_kernel(float* __restrict__ bias,
                                     const float* __restrict__ beta,
                                     const float* __restrict__ mean,
                                     const float* __restrict__ gamma,
                                     const float* __restrict__ rvar)
{
    int j = blockIdx.x * blockDim.x + threadIdx.x;
    if (j < DIM_D) {
        float s = gamma[j] * rsqrtf(rvar[j] + BN_EPS);
        bias[j] = beta[j] + s * (bias[j] - mean[j]);
    }
}

// ------------------------------- launcher ----------------------------------

extern "C" void kernel_launch(void* const* d_in, const int* in_sizes, int n_in,
                              void* d_out, int out_size)
{
    const float* kmer  = (const float*)d_in[0];
    const float* cov   = (const float*)d_in[1];
    const float* Wk    = (const float*)d_in[2];
    const float* bk    = (const float*)d_in[3];
    const float* Wc    = (const float*)d_in[4];
    const float* bc    = (const float*)d_in[5];
    const float* Wv    = (const float*)d_in[6];
    const float* bv    = (const float*)d_in[7];
    const float* Wo    = (const float*)d_in[8];
    const float* bo    = (const float*)d_in[9];
    const float* Wf    = (const float*)d_in[10];
    const float* bf    = (const float*)d_in[11];
    const float* gamma = (const float*)d_in[12];
    const float* beta  = (const float*)d_in[13];
    const float* mean  = (const float*)d_in[14];
    const float* var   = (const float*)d_in[15];
    float* out = (float*)d_out;

    __half *Xh, *Wh;
    float *WcT, *WkT, *M1t, *M2t, *bias, *t1, *t2;
    cudaGetSymbolAddress((void**)&Xh,   g_Xh);
    cudaGetSymbolAddress((void**)&Wh,   g_Wh);
    cudaGetSymbolAddress((void**)&WcT,  g_WcT);
    cudaGetSymbolAddress((void**)&WkT,  g_WkT);
    cudaGetSymbolAddress((void**)&M1t,  g_M1t);
    cudaGetSymbolAddress((void**)&M2t,  g_M2t);
    cudaGetSymbolAddress((void**)&bias, g_bias);
    cudaGetSymbolAddress((void**)&t1,   g_t1);
    cudaGetSymbolAddress((void**)&t2,   g_t2);

    cudaFuncSetAttribute(gemm_nt_kernel<1>, cudaFuncAttributeMaxDynamicSharedMemorySize, GSMEM_TOTAL);
    cudaFuncSetAttribute(gemm_nt_kernel<2>, cudaFuncAttributeMaxDynamicSharedMemorySize, GSMEM_TOTAL);
    cudaFuncSetAttribute(main_gemm_fp16,    cudaFuncAttributeMaxDynamicSharedMemorySize, HSMEM_TOTAL);

    // 0,1: activation pack (fp32 -> fp16, permuted)
    pack_fp16<<<4096, 256>>>(kmer, 12, 0,        Xh);
    pack_fp16<<<1024, 256>>>(cov,  10, DIM_KMER, Xh);

    // 2,3: transposes for NT weight GEMMs
    {
        dim3 blk(32, 8);
        dim3 gc(DIM_COV / 32,  DIM_D / 32);
        dim3 gk(DIM_KMER / 32, DIM_D / 32);
        transpose_kernel<<<gc, blk>>>(Wc, WcT, DIM_D, DIM_COV);
        transpose_kernel<<<gk, blk>>>(Wk, WkT, DIM_D, DIM_KMER);
    }

    // 4: M1t = (Wv @ Wc)^T
    {
        dim3 grid(DIM_COV / 128, DIM_D / 128);
        gemm_nt_kernel<1><<<grid, 128, GSMEM_TOTAL>>>(
            Wv, DIM_D, WcT, DIM_D, M1t, DIM_D, 0, DIM_D, nullptr, nullptr);
    }
    // 5: Wh left = fp16(s*(Wf_l @ Wk))   (big one — ncu -s 5 lands here)
    {
        dim3 grid(DIM_KMER / 128, DIM_D / 128);
        gemm_nt_kernel<2><<<grid, 128, GSMEM_TOTAL>>>(
            Wf, 2 * DIM_D, WkT, DIM_D, (float*)Wh, DIM_KTOT / 2, 0, DIM_D, gamma, var);
    }
    // 6: M2t = (Wo @ M1)^T
    {
        dim3 grid(DIM_COV / 128, DIM_D / 128);
        gemm_nt_kernel<1><<<grid, 128, GSMEM_TOTAL>>>(
            Wo, DIM_D, M1t, DIM_D, M2t, DIM_D, 0, DIM_D, nullptr, nullptr);
    }
    // 7: Wh right = fp16(s*(Wf_r @ M2))
    {
        dim3 grid(DIM_COV / 128, DIM_D / 128);
        gemm_nt_kernel<2><<<grid, 128, GSMEM_TOTAL>>>(
            Wf + DIM_D, 2 * DIM_D, M2t, DIM_D, (float*)Wh, DIM_KTOT / 2, DIM_KMER, DIM_D, gamma, var);
    }

    // 8-11: bias chain
    matvec_kernel<<<DIM_D, 256>>>(Wv, DIM_D, 0,          bc, DIM_D, bv,      t1,   0);
    matvec_kernel<<<DIM_D, 256>>>(Wo, DIM_D, 0,          t1, DIM_D, bo,      t2,   0);
    matvec_kernel<<<DIM_D, 256>>>(Wf, 2 * DIM_D, DIM_D,  t2, DIM_D, bf,      bias, 0);
    matvec_kernel<<<DIM_D, 256>>>(Wf, 2 * DIM_D, 0,      bk, DIM_D, nullptr, bias, 1);

    // 12: fold BN into bias
    bias_finalize_kernel<<<(DIM_D + 255) / 256, 256>>>(bias, beta, mean, gamma, var);

    // 13: main fused GEMM (fp16 mma) + bias + ReLU
    {
        dim3 grid(DIM_D / 128, DIM_B / 128);   // (16, 128)
        main_gemm_fp16<<<grid, 128, HSMEM_TOTAL>>>(Xh, Wh, bias, out);
    }
}

// round 6
// speedup vs baseline: 2.5397x; 1.1727x over previous
#include <cuda_runtime.h>
#include <cuda_fp16.h>
#include <cstdint>

// ---------------------------------------------------------------------------
// FusionLayer collapsed to: out = relu(X @ Wcat^T + bias')
// EVERYTHING (main + weight composition) on one fp16 m16n8k16 NT GEMM core
// (fp32 accumulate). All fp16 operands stored b32-permuted in 32-col groups:
// dst b32 (4t+s) = orig b32 (t+4s), so one LDS.128 feeds a thread's fragment
// regs for two k16 groups. Chain computed transpose-free by operand flipping:
//   M1th = core(WcTh, Wvh); M2th = core(M1th, Woh)
//   Wh[:, :4096]  = s * core(Wfh_left,  WkTh)
//   Wh[:, 4096:]  = s * core(Wfh_right, M2th)
// ---------------------------------------------------------------------------

#define DIM_B    16384
#define DIM_KMER 4096
#define DIM_COV  1024
#define DIM_D    2048
#define DIM_KTOT 5120
#define BN_EPS   1e-5f

// scratch (allocation-free rule: __device__ globals)
__device__ __half g_Xh[(size_t)DIM_B * DIM_KTOT];   // fp16 perm activations
__device__ __half g_Wh[DIM_D * DIM_KTOT];           // fp16 perm [A' | B']
__device__ __half g_Wvh[DIM_D * DIM_D];
__device__ __half g_Woh[DIM_D * DIM_D];
__device__ __half g_Wfh[DIM_D * 2 * DIM_D];
__device__ __half g_WcTh[DIM_COV * DIM_D];
__device__ __half g_WkTh[DIM_KMER * DIM_D];
__device__ __half g_M1th[DIM_COV * DIM_D];
__device__ __half g_M2th[DIM_COV * DIM_D];
__device__ float  g_WcT[DIM_COV * DIM_D];
__device__ float  g_WkT[DIM_KMER * DIM_D];
__device__ float  g_bias[DIM_D];
__device__ float  g_t1[DIM_D];
__device__ float  g_t2[DIM_D];

// ------------------------------- helpers -----------------------------------

__device__ __forceinline__ uint32_t smem_cast(const void* p) {
    uint32_t r;
    asm volatile("{ .reg .u64 t; cvta.to.shared.u64 t, %1; cvt.u32.u64 %0, t; }"
                 : "=r"(r) : "l"(p));
    return r;
}

__device__ __forceinline__ void cp_async16(void* sdst, const void* gsrc) {
    uint32_t d = smem_cast(sdst);
    asm volatile("cp.async.cg.shared.global [%0], [%1], 16;\n" :: "r"(d), "l"(gsrc));
}

__device__ __forceinline__ void mma_fp16(float c[4], uint32_t a0, uint32_t a1,
                                         uint32_t a2, uint32_t a3,
                                         uint32_t b0, uint32_t b1) {
    asm volatile(
        "mma.sync.aligned.m16n8k16.row.col.f32.f16.f16.f32 "
        "{%0,%1,%2,%3}, {%4,%5,%6,%7}, {%8,%9}, {%0,%1,%2,%3};\n"
        : "+f"(c[0]), "+f"(c[1]), "+f"(c[2]), "+f"(c[3])
        : "r"(a0), "r"(a1), "r"(a2), "r"(a3), "r"(b0), "r"(b1));
}

__device__ __forceinline__ uint32_t pack_h2(float lo, float hi) {
    __half2 h = __floats2half2_rn(lo, hi);
    return *reinterpret_cast<uint32_t*>(&h);
}

// ===================== unified fp16 NT GEMM core ============================
// C-tile 128x128, 4 warps of 64x64, BK=64 (128B rows), 3-stage cp.async.
// smem rows XOR-swizzled by 64B on odd rows (conflict-free uint4 LDS).
// EPI 0: fp32 bias+relu store (aux1 = bias, ldc in floats)
// EPI 1: fp16 b32-permuted store (C as uint32_t*, ldc in b32 units);
//        optional per-row BN scale if aux1 != nullptr (aux1=gamma, aux2=var)

#define HSTG 3
#define HSTAGE_BYTES 32768            // A 16KB + B 16KB
#define HSMEM_TOTAL (HSTG * HSTAGE_BYTES)

template<int EPI>
__global__ void __launch_bounds__(128, 2)
gemm_h_kernel(const __half* __restrict__ A, int lda,
              const __half* __restrict__ Bt, int ldb,
              void* __restrict__ Cv, int ldc, int coffs, int K,
              const float* __restrict__ aux1, const float* __restrict__ aux2)
{
    extern __shared__ char smem[];
    const int tid  = threadIdx.x;
    const int lane = tid & 31;
    const int wid  = tid >> 5;
    const int wm   = wid >> 1;
    const int wn   = wid & 1;
    const int g    = lane >> 2;
    const int tg   = lane & 3;
    const int bn   = blockIdx.x, bm = blockIdx.y;

    const __half* gA = A  + (size_t)(bm * 128) * lda;
    const __half* gB = Bt + (size_t)(bn * 128) * ldb;

    float acc[4][8][4];
#pragma unroll
    for (int i = 0; i < 4; i++)
#pragma unroll
        for (int j = 0; j < 8; j++)
#pragma unroll
            for (int q = 0; q < 4; q++) acc[i][j][q] = 0.f;

    auto load_tile = [&](int slot, int kt) {
        char* stg = smem + slot * HSTAGE_BYTES;
        const int k0 = kt * 64;
#pragma unroll
        for (int i = 0; i < 8; i++) {            // A: 128 rows x 128B
            int fid = tid + i * 128;
            int row = fid >> 3, c = fid & 7;
            cp_async16(stg + row * 128 + ((c * 16) ^ ((row & 1) << 6)),
                       gA + (size_t)row * lda + k0 + c * 8);
        }
#pragma unroll
        for (int i = 0; i < 8; i++) {            // B
            int fid = tid + i * 128;
            int row = fid >> 3, c = fid & 7;
            cp_async16(stg + 16384 + row * 128 + ((c * 16) ^ ((row & 1) << 6)),
                       gB + (size_t)row * ldb + k0 + c * 8);
        }
        asm volatile("cp.async.commit_group;\n");
    };

    const int NKT = K / 64;
    load_tile(0, 0);
    load_tile(1, 1);

    for (int kt = 0; kt < NKT; kt++) {
        asm volatile("cp.async.wait_group %0;\n" :: "n"(1));
        __syncthreads();
        if (kt + 2 < NKT) load_tile((kt + 2) % HSTG, kt + 2);
        else asm volatile("cp.async.commit_group;\n");

        const char* pa = smem + (kt % HSTG) * HSTAGE_BYTES;
        const char* pb = pa + 16384;

#pragma unroll
        for (int b = 0; b < 2; b++) {            // two 64B (k32) blocks
            uint4 Af[8], Bf[8];
#pragma unroll
            for (int mt = 0; mt < 4; mt++) {
                int r0 = wm * 64 + mt * 16 + g;
                int r1 = r0 + 8;
                Af[2 * mt] = *reinterpret_cast<const uint4*>(
                    pa + r0 * 128 + ((b * 64 + tg * 16) ^ ((r0 & 1) << 6)));
                Af[2 * mt + 1] = *reinterpret_cast<const uint4*>(
                    pa + r1 * 128 + ((b * 64 + tg * 16) ^ ((r1 & 1) << 6)));
            }
#pragma unroll
            for (int nt = 0; nt < 8; nt++) {
                int r = wn * 64 + nt * 8 + g;
                Bf[nt] = *reinterpret_cast<const uint4*>(
                    pb + r * 128 + ((b * 64 + tg * 16) ^ ((r & 1) << 6)));
            }
            // permuted layout: .x/.y = k16-group0 (lo/hi), .z/.w = group1
#pragma unroll
            for (int grp = 0; grp < 2; grp++) {
#pragma unroll
                for (int mt = 0; mt < 4; mt++) {
                    uint32_t a0, a1, a2, a3;
                    if (grp == 0) {
                        a0 = Af[2 * mt].x; a1 = Af[2 * mt + 1].x;
                        a2 = Af[2 * mt].y; a3 = Af[2 * mt + 1].y;
                    } else {
                        a0 = Af[2 * mt].z; a1 = Af[2 * mt + 1].z;
                        a2 = Af[2 * mt].w; a3 = Af[2 * mt + 1].w;
                    }
#pragma unroll
                    for (int nt = 0; nt < 8; nt++) {
                        uint32_t b0, b1;
                        if (grp == 0) { b0 = Bf[nt].x; b1 = Bf[nt].y; }
                        else          { b0 = Bf[nt].z; b1 = Bf[nt].w; }
                        mma_fp16(acc[mt][nt], a0, a1, a2, a3, b0, b1);
                    }
                }
            }
        }
    }

    // ------------------------------ epilogue --------------------------------
#pragma unroll
    for (int mt = 0; mt < 4; mt++) {
        const int row = bm * 128 + wm * 64 + mt * 16 + g;
        float s0 = 1.f, s1 = 1.f;
        if (EPI == 1 && aux1 != nullptr) {
            s0 = aux1[row]     * rsqrtf(aux2[row]     + BN_EPS);
            s1 = aux1[row + 8] * rsqrtf(aux2[row + 8] + BN_EPS);
        }
#pragma unroll
        for (int nt = 0; nt < 8; nt++) {
            const int col = bn * 128 + wn * 64 + nt * 8 + tg * 2;
            if (EPI == 0) {
                float* C = reinterpret_cast<float*>(Cv);
                float b0 = aux1[col], b1 = aux1[col + 1];
                float2 v;
                v.x = fmaxf(acc[mt][nt][0] + b0, 0.f);
                v.y = fmaxf(acc[mt][nt][1] + b1, 0.f);
                *reinterpret_cast<float2*>(&C[(size_t)row * ldc + col]) = v;
                v.x = fmaxf(acc[mt][nt][2] + b0, 0.f);
                v.y = fmaxf(acc[mt][nt][3] + b1, 0.f);
                *reinterpret_cast<float2*>(&C[(size_t)(row + 8) * ldc + col]) = v;
            } else {
                uint32_t* Ch = reinterpret_cast<uint32_t*>(Cv);
                int j = (coffs + col) >> 1;                 // global b32 index
                int dst = (j & ~15) + 4 * (j & 3) + ((j & 15) >> 2);
                Ch[(size_t)row * ldc + dst]       = pack_h2(acc[mt][nt][0] * s0,
                                                            acc[mt][nt][1] * s0);
                Ch[(size_t)(row + 8) * ldc + dst] = pack_h2(acc[mt][nt][2] * s1,
                                                            acc[mt][nt][3] * s1);
            }
        }
    }
}

// ============= pack row-major fp32 -> fp16, b32-permuted ====================
// one thread per 32-col block: dst uint4 t = {h[t], h[t+4], h[t+8], h[t+12]}

__global__ void pack_fp16(const float* __restrict__ src, int lw, size_t nrows,
                          __half* __restrict__ dst, int dst_stride, int dstoff)
{
    const int nblk = 1 << (lw - 5);
    const size_t total = nrows << (lw - 5);
    for (size_t idx = (size_t)blockIdx.x * blockDim.x + threadIdx.x; idx < total;
         idx += (size_t)gridDim.x * blockDim.x) {
        const size_t b = idx >> (lw - 5);
        const int blk  = (int)(idx & (nblk - 1));
        const float4* s = reinterpret_cast<const float4*>(src + (b << lw) + blk * 32);
        uint32_t h[16];
#pragma unroll
        for (int i = 0; i < 8; i++) {
            float4 v = s[i];
            h[2 * i]     = pack_h2(v.x, v.y);
            h[2 * i + 1] = pack_h2(v.z, v.w);
        }
        uint4* d = reinterpret_cast<uint4*>(dst + b * dst_stride + dstoff + blk * 32);
#pragma unroll
        for (int t = 0; t < 4; t++)
            d[t] = make_uint4(h[t], h[t + 4], h[t + 8], h[t + 12]);
    }
}

// ============================ transpose =====================================

__global__ void transpose_kernel(const float* __restrict__ in, float* __restrict__ outT,
                                 int R, int Cc)
{
    __shared__ float t[32][33];
    const int bx = blockIdx.x * 32, by = blockIdx.y * 32;
    int x = bx + threadIdx.x;
    int y = by + threadIdx.y;
#pragma unroll
    for (int j = 0; j < 32; j += 8)
        t[threadIdx.y + j][threadIdx.x] = in[(size_t)(y + j) * Cc + x];
    __syncthreads();
    x = by + threadIdx.x;
    y = bx + threadIdx.y;
#pragma unroll
    for (int j = 0; j < 32; j += 8)
        outT[(size_t)(y + j) * R + x] = t[threadIdx.x][threadIdx.y + j];
}

// ============================ bias chain ====================================

__global__ void matvec_kernel(const float* __restrict__ A, int lda, int aoffs,
                              const float* __restrict__ x, int K,
                              const float* __restrict__ addv,
                              float* __restrict__ y, int accum)
{
    int i = blockIdx.x;
    const float* arow = A + (size_t)i * lda + aoffs;
    float s = 0.f;
    for (int k = threadIdx.x; k < K; k += blockDim.x) s += arow[k] * x[k];
#pragma unroll
    for (int o = 16; o > 0; o >>= 1) s += __shfl_xor_sync(0xffffffffu, s, o);
    __shared__ float red[8];
    if ((threadIdx.x & 31) == 0) red[threadIdx.x >> 5] = s;
    __syncthreads();
    if (threadIdx.x == 0) {
        float t = 0.f;
        for (int w = 0; w < (int)(blockDim.x >> 5); w++) t += red[w];
        if (addv) t += addv[i];
        if (accum) t += y[i];
        y[i] = t;
    }
}

__global__ void bias_finalize_kernel(float* __restrict__ bias,
                                     const float* __restrict__ beta,
                                     const float* __restrict__ mean,
                                     const float* __restrict__ gamma,
                                     const float* __restrict__ rvar)
{
    int j = blockIdx.x * blockDim.x + threadIdx.x;
    if (j < DIM_D) {
        float s = gamma[j] * rsqrtf(rvar[j] + BN_EPS);
        bias[j] = beta[j] + s * (bias[j] - mean[j]);
    }
}

// ------------------------------- launcher ----------------------------------

extern "C" void kernel_launch(void* const* d_in, const int* in_sizes, int n_in,
                              void* d_out, int out_size)
{
    const float* kmer  = (const float*)d_in[0];
    const float* cov   = (const float*)d_in[1];
    const float* Wk    = (const float*)d_in[2];
    const float* bk    = (const float*)d_in[3];
    const float* Wc    = (const float*)d_in[4];
    const float* bc    = (const float*)d_in[5];
    const float* Wv    = (const float*)d_in[6];
    const float* bv    = (const float*)d_in[7];
    const float* Wo    = (const float*)d_in[8];
    const float* bo    = (const float*)d_in[9];
    const float* Wf    = (const float*)d_in[10];
    const float* bf    = (const float*)d_in[11];
    const float* gamma = (const float*)d_in[12];
    const float* beta  = (const float*)d_in[13];
    const float* mean  = (const float*)d_in[14];
    const float* var   = (const float*)d_in[15];
    float* out = (float*)d_out;

    __half *Xh, *Wh, *Wvh, *Woh, *Wfh, *WcTh, *WkTh, *M1th, *M2th;
    float *WcT, *WkT, *bias, *t1, *t2;
    cudaGetSymbolAddress((void**)&Xh,   g_Xh);
    cudaGetSymbolAddress((void**)&Wh,   g_Wh);
    cudaGetSymbolAddress((void**)&Wvh,  g_Wvh);
    cudaGetSymbolAddress((void**)&Woh,  g_Woh);
    cudaGetSymbolAddress((void**)&Wfh,  g_Wfh);
    cudaGetSymbolAddress((void**)&WcTh, g_WcTh);
    cudaGetSymbolAddress((void**)&WkTh, g_WkTh);
    cudaGetSymbolAddress((void**)&M1th, g_M1th);
    cudaGetSymbolAddress((void**)&M2th, g_M2th);
    cudaGetSymbolAddress((void**)&WcT,  g_WcT);
    cudaGetSymbolAddress((void**)&WkT,  g_WkT);
    cudaGetSymbolAddress((void**)&bias, g_bias);
    cudaGetSymbolAddress((void**)&t1,   g_t1);
    cudaGetSymbolAddress((void**)&t2,   g_t2);

    cudaFuncSetAttribute(gemm_h_kernel<0>, cudaFuncAttributeMaxDynamicSharedMemorySize, HSMEM_TOTAL);
    cudaFuncSetAttribute(gemm_h_kernel<1>, cudaFuncAttributeMaxDynamicSharedMemorySize, HSMEM_TOTAL);

    // activation pack (fp32 -> fp16 permuted)
    pack_fp16<<<4096, 256>>>(kmer, 12, DIM_B, Xh, DIM_KTOT, 0);
    pack_fp16<<<1024, 256>>>(cov,  10, DIM_B, Xh, DIM_KTOT, DIM_KMER);

    // transposes (fp32), then packs to fp16 permuted
    {
        dim3 blk(32, 8);
        dim3 gc(DIM_COV / 32,  DIM_D / 32);
        dim3 gk(DIM_KMER / 32, DIM_D / 32);
        transpose_kernel<<<gc, blk>>>(Wc, WcT, DIM_D, DIM_COV);
        transpose_kernel<<<gk, blk>>>(Wk, WkT, DIM_D, DIM_KMER);
    }
    pack_fp16<<< 512, 256>>>(WcT, 11, DIM_COV,  WcTh, DIM_D, 0);
    pack_fp16<<<2048, 256>>>(WkT, 11, DIM_KMER, WkTh, DIM_D, 0);
    pack_fp16<<<1024, 256>>>(Wv,  11, DIM_D,    Wvh,  DIM_D, 0);
    pack_fp16<<<1024, 256>>>(Wo,  11, DIM_D,    Woh,  DIM_D, 0);
    pack_fp16<<<2048, 256>>>(Wf,  12, DIM_D,    Wfh,  2 * DIM_D, 0);

    // weight composition (all on fp16 core, no transposed stores)
    // G1: M1th[j,i] = sum_k WcT[j,k] * Wv[i,k]
    {
        dim3 grid(DIM_D / 128, DIM_COV / 128);   // (16, 8)
        gemm_h_kernel<1><<<grid, 128, HSMEM_TOTAL>>>(
            WcTh, DIM_D, Wvh, DIM_D, M1th, DIM_D / 2, 0, DIM_D, nullptr, nullptr);
    }
    // G2: M2th[j,i] = sum_k M1th[j,k] * Wo[i,k]
    {
        dim3 grid(DIM_D / 128, DIM_COV / 128);   // (16, 8)
        gemm_h_kernel<1><<<grid, 128, HSMEM_TOTAL>>>(
            M1th, DIM_D, Woh, DIM_D, M2th, DIM_D / 2, 0, DIM_D, nullptr, nullptr);
    }
    // G3: Wh[:, 0:4096] = s * (Wf_l @ Wk):  A=Wfh_left, Bt=WkTh
    {
        dim3 grid(DIM_KMER / 128, DIM_D / 128);  // (32, 16)
        gemm_h_kernel<1><<<grid, 128, HSMEM_TOTAL>>>(
            Wfh, 2 * DIM_D, WkTh, DIM_D, Wh, DIM_KTOT / 2, 0, DIM_D, gamma, var);
    }
    // G4: Wh[:, 4096:5120] = s * (Wf_r @ M2):  A=Wfh_right, Bt=M2th
    {
        dim3 grid(DIM_COV / 128, DIM_D / 128);   // (8, 16)
        gemm_h_kernel<1><<<grid, 128, HSMEM_TOTAL>>>(
            Wfh + DIM_D, 2 * DIM_D, M2th, DIM_D, Wh, DIM_KTOT / 2, DIM_KMER, DIM_D, gamma, var);
    }

    // bias chain (fp32, original weights)
    matvec_kernel<<<DIM_D, 256>>>(Wv, DIM_D, 0,          bc, DIM_D, bv,      t1,   0);
    matvec_kernel<<<DIM_D, 256>>>(Wo, DIM_D, 0,          t1, DIM_D, bo,      t2,   0);
    matvec_kernel<<<DIM_D, 256>>>(Wf, 2 * DIM_D, DIM_D,  t2, DIM_D, bf,      bias, 0);
    matvec_kernel<<<DIM_D, 256>>>(Wf, 2 * DIM_D, 0,      bk, DIM_D, nullptr, bias, 1);
    bias_finalize_kernel<<<(DIM_D + 255) / 256, 256>>>(bias, beta, mean, gamma, var);

    // main fused GEMM + bias + ReLU
    {
        dim3 grid(DIM_D / 128, DIM_B / 128);     // (16, 128)
        gemm_h_kernel<0><<<grid, 128, HSMEM_TOTAL>>>(
            Xh, DIM_KTOT, Wh, DIM_KTOT, out, DIM_D, 0, DIM_KTOT, bias, nullptr);
    }
}